// round 9
// baseline (speedup 1.0000x reference)
#include <cuda_runtime.h>
#include <cuda_bf16.h>
#include <math.h>
#include <stdint.h>

#define B_  4
#define C_  64
#define T_  128
#define Fd_ 128
#define H_  128
#define K_  8
#define L_  121              // F - K + 1
#define N_  (B_*T_)          // 512
#define M_  (L_*N_)          // 61952
#define CK_ (C_*K_)          // 512

// weight scratch offsets (elements) for transposed int8 weights [N][K]
#define WOFF0 0
#define WOFF1 (1024*512)
#define WOFF2 (WOFF1 + 1024*256)
#define WOFF3 (WOFF2 + 1024*256)
#define WOFFC (WOFF3 + 1024*256)
#define WTOT  (WOFFC + 512*256)
// per-matrix scale row offsets
#define SOFF0 0
#define SOFF1 1024
#define SOFF2 2048
#define SOFF3 3072
#define SOFFC 4096
#define STOT  (4096 + 512)

// ---- scratch (device globals; no allocation allowed) ----
__device__ float  g_xn [B_*C_*T_*Fd_];   // 16.8 MB  normed input (fp32, for residual)
__device__ int8_t g_aqh[M_*CK_];         // 31.7 MB  activation int8 hi (h0 or h)
__device__ int8_t g_aql[M_*CK_];         // 31.7 MB  activation int8 lo
__device__ float  g_hf [M_*2*H_];        // 63.4 MB  scan output fp32 (quant source)
__device__ float  g_U  [M_*8*H_];        // 253.8 MB GEMM output (fp32)
__device__ int8_t g_wqh[WTOT];           // transposed weights int8 hi
__device__ int8_t g_wql[WTOT];           // transposed weights int8 lo
__device__ float  g_sa [M_];             // per-row activation scales
__device__ float  g_sw [STOT];           // per-row weight scales

// ============================ helpers ============================
__device__ __forceinline__ uint32_t smem_u32(const void* p) {
    uint32_t a;
    asm("{ .reg .u64 t; cvta.to.shared.u64 t, %1; cvt.u32.u64 %0, t; }" : "=r"(a) : "l"(p));
    return a;
}
__device__ __forceinline__ void cp16(uint32_t s, const void* g) {
    asm volatile("cp.async.cg.shared.global [%0], [%1], 16;" :: "r"(s), "l"(g) : "memory");
}
#define CP_COMMIT() asm volatile("cp.async.commit_group;" ::: "memory")

__device__ __forceinline__ void ldsm4(uint32_t* r, uint32_t addr) {
    asm volatile("ldmatrix.sync.aligned.m8n8.x4.shared.b16 {%0,%1,%2,%3}, [%4];"
        : "=r"(r[0]), "=r"(r[1]), "=r"(r[2]), "=r"(r[3]) : "r"(addr));
}
// int8 MMA: m16n8k32 s8*s8 -> s32
__device__ __forceinline__ void imma(int* c, const uint32_t* a, uint32_t b0, uint32_t b1) {
    asm volatile("mma.sync.aligned.m16n8k32.row.col.s32.s8.s8.s32 "
        "{%0,%1,%2,%3}, {%4,%5,%6,%7}, {%8,%9}, {%0,%1,%2,%3};"
        : "+r"(c[0]), "+r"(c[1]), "+r"(c[2]), "+r"(c[3])
        : "r"(a[0]), "r"(a[1]), "r"(a[2]), "r"(a[3]), "r"(b0), "r"(b1));
}

// two-level int8 quantization: v ~= s*hi + (s/256)*lo
__device__ __forceinline__ void q2(float v, float inv, int& qh, int& ql) {
    float q = v * inv;
    int hi = __float2int_rn(q);
    hi = min(127, max(-127, hi));
    int lo = __float2int_rn((q - (float)hi) * 256.f);
    lo = min(127, max(-127, lo));
    qh = hi; ql = lo;
}

// ============================ channel norm ============================
__global__ void knorm(const float* __restrict__ x, const float* __restrict__ gamma,
                      const float* __restrict__ beta) {
    int idx = blockIdx.x * blockDim.x + threadIdx.x;   // over B*T*F
    if (idx >= B_*T_*Fd_) return;
    int f = idx % Fd_;
    int t = (idx / Fd_) % T_;
    int b = idx / (T_*Fd_);
    float v[C_];
    float s = 0.f;
#pragma unroll
    for (int c = 0; c < C_; ++c) {
        v[c] = x[((b*C_ + c)*T_ + t)*Fd_ + f];
        s += v[c];
    }
    float mu = s * (1.0f/C_);
    float vs = 0.f;
#pragma unroll
    for (int c = 0; c < C_; ++c) { float d = v[c]-mu; vs += d*d; }
    float inv = rsqrtf(vs*(1.0f/C_) + 1e-8f);
#pragma unroll
    for (int c = 0; c < C_; ++c) {
        g_xn[((b*C_ + c)*T_ + t)*Fd_ + f] = gamma[c]*(v[c]-mu)*inv + beta[c];
    }
}

// ============ unfold row + per-row quantize: one block per m-row ============
__global__ __launch_bounds__(128) void kunfold_q() {
    int m   = blockIdx.x;
    int tid = threadIdx.x;               // 128 threads, 4 elems each
    int n = m % N_, l = m / N_;
    int b = n >> 7, t = n & 127;
    int ck0 = tid * 4;
    int c = ck0 >> 3, k = ck0 & 7;       // 4 consecutive ck share c
    const float* src = &g_xn[((b*C_ + c)*T_ + t)*Fd_ + l + k];
    float v[4];
#pragma unroll
    for (int j = 0; j < 4; ++j) v[j] = src[j];
    float mx = fmaxf(fmaxf(fabsf(v[0]), fabsf(v[1])), fmaxf(fabsf(v[2]), fabsf(v[3])));
#pragma unroll
    for (int o = 16; o; o >>= 1) mx = fmaxf(mx, __shfl_xor_sync(~0u, mx, o));
    __shared__ float red[4];
    if ((tid & 31) == 0) red[tid >> 5] = mx;
    __syncthreads();
    mx = fmaxf(fmaxf(red[0], red[1]), fmaxf(red[2], red[3]));
    mx = fmaxf(mx, 1e-20f);
    float s = mx * (1.f/127.f), inv = 127.f / mx;
    int qh[4], ql[4];
#pragma unroll
    for (int j = 0; j < 4; ++j) q2(v[j], inv, qh[j], ql[j]);
    *(char4*)&g_aqh[(size_t)m*CK_ + ck0] = make_char4((char)qh[0], (char)qh[1], (char)qh[2], (char)qh[3]);
    *(char4*)&g_aql[(size_t)m*CK_ + ck0] = make_char4((char)ql[0], (char)ql[1], (char)ql[2], (char)ql[3]);
    if (tid == 0) g_sa[m] = s;
}

// ============ quantize scan output rows (256 cols): one block per m-row ============
__global__ __launch_bounds__(64) void kaq() {
    int m   = blockIdx.x;
    int tid = threadIdx.x;               // 64 threads, 4 elems each
    const float* row = &g_hf[(size_t)m * 256];
    float v[4];
#pragma unroll
    for (int j = 0; j < 4; ++j) v[j] = row[tid*4 + j];
    float mx = fmaxf(fmaxf(fabsf(v[0]), fabsf(v[1])), fmaxf(fabsf(v[2]), fabsf(v[3])));
#pragma unroll
    for (int o = 16; o; o >>= 1) mx = fmaxf(mx, __shfl_xor_sync(~0u, mx, o));
    __shared__ float red[2];
    if ((tid & 31) == 0) red[tid >> 5] = mx;
    __syncthreads();
    mx = fmaxf(fmaxf(red[0], red[1]), 1e-20f);
    float s = mx * (1.f/127.f), inv = 127.f / mx;
    int qh[4], ql[4];
#pragma unroll
    for (int j = 0; j < 4; ++j) q2(v[j], inv, qh[j], ql[j]);
    *(char4*)&g_aqh[(size_t)m*256 + tid*4] = make_char4((char)qh[0], (char)qh[1], (char)qh[2], (char)qh[3]);
    *(char4*)&g_aql[(size_t)m*256 + tid*4] = make_char4((char)ql[0], (char)ql[1], (char)ql[2], (char)ql[3]);
    if (tid == 0) g_sa[m] = s;
}

// ============ weight transpose + per-row quantize: W (R x Cc) -> Bt[n][k] ============
__global__ __launch_bounds__(128) void kwq(const float* __restrict__ W,
                                           int8_t* __restrict__ bh, int8_t* __restrict__ bl,
                                           float* __restrict__ sb, int R, int Cc) {
    int n   = blockIdx.x;                // output row (gemm column)
    int tid = threadIdx.x;               // 128 threads
    int per = R >> 7;                    // 4 (R=512) or 2 (R=256)
    float v[4];
    float mx = 0.f;
    for (int j = 0; j < per; ++j) {
        v[j] = W[(size_t)(tid + j*128)*Cc + n];
        mx = fmaxf(mx, fabsf(v[j]));
    }
#pragma unroll
    for (int o = 16; o; o >>= 1) mx = fmaxf(mx, __shfl_xor_sync(~0u, mx, o));
    __shared__ float red[4];
    if ((tid & 31) == 0) red[tid >> 5] = mx;
    __syncthreads();
    mx = fmaxf(fmaxf(red[0], red[1]), fmaxf(red[2], red[3]));
    mx = fmaxf(mx, 1e-20f);
    float s = mx * (1.f/127.f), inv = 127.f / mx;
    for (int j = 0; j < per; ++j) {
        int qh, ql;
        q2(v[j], inv, qh, ql);
        bh[(size_t)n*R + tid + j*128] = (int8_t)qh;
        bl[(size_t)n*R + tid + j*128] = (int8_t)ql;
    }
    if (tid == 0) sb[n] = s;
}

// ============================ int8 split GEMM ============================
// C(M x N) = A(M x K)*B(K x N); A int8 hi/lo [M][K], B int8 hi/lo transposed [N][K].
// CTA tile 128x128, warp tile 32x64, 8 warps, BK=64 int8 (two k32 steps).
// SMEM stage: AH|AL|BH|BL, each 128 rows x 80B (64B data + 16 pad).
#define ROWB   80
#define MATB   (128*ROWB)              // 10240
#define SB_AH  0
#define SB_AL  MATB
#define SB_BH  (2*MATB)
#define SB_BL  (3*MATB)
#define STAGEB (4*MATB)                // 40960
#define NSTAGE 3
#define GEMM_DSMEM (NSTAGE*STAGEB)     // 122880

__device__ __forceinline__ void load_stage(uint32_t sb, int k0,
    const int8_t* __restrict__ Ah, const int8_t* __restrict__ Al,
    const int8_t* __restrict__ Bh, const int8_t* __restrict__ Bl,
    int K, int bm, int bn, int tid) {
#pragma unroll
    for (int i = tid; i < 512; i += 256) {
        int row = i >> 2, ch = i & 3;
        uint32_t so = (uint32_t)(row*ROWB + ch*16);
        size_t ga = (size_t)(bm + row)*K + k0 + ch*16;
        size_t gb = (size_t)(bn + row)*K + k0 + ch*16;
        cp16(sb + SB_AH + so, Ah + ga);
        cp16(sb + SB_AL + so, Al + ga);
        cp16(sb + SB_BH + so, Bh + gb);
        cp16(sb + SB_BL + so, Bl + gb);
    }
}

__global__ __launch_bounds__(256) void kgemm(
    const int8_t* __restrict__ Ah, const int8_t* __restrict__ Al,
    const int8_t* __restrict__ Bh, const int8_t* __restrict__ Bl,
    const float* __restrict__ sA, const float* __restrict__ sB,
    float* __restrict__ U, int K, int Nld) {
    extern __shared__ char dsm[];
    uint32_t dyn = smem_u32(dsm);
    int tid  = threadIdx.x;
    int wid  = tid >> 5, lane = tid & 31;
    int bm   = blockIdx.y * 128, bn = blockIdx.x * 128;
    int wm   = (wid >> 1) * 32;        // warp m offset (0,32,64,96)
    int wn   = (wid & 1)  * 64;        // warp n offset (0,64)

    // ldmatrix lane selectors (16-row x 32-byte tiles)
    int g = lane >> 3;
    int lrow = (g & 1) * 8 + (lane & 7);
    int lsel = g >> 1;

    int acch[2][8][4], accc[2][8][4];
#pragma unroll
    for (int i = 0; i < 2; ++i)
#pragma unroll
        for (int j = 0; j < 8; ++j)
#pragma unroll
            for (int q = 0; q < 4; ++q) { acch[i][j][q] = 0; accc[i][j][q] = 0; }

    int nc = K >> 6;                    // BK=64 chunks
#pragma unroll
    for (int s = 0; s < NSTAGE - 1; ++s) {
        load_stage(dyn + s*STAGEB, s*64, Ah, Al, Bh, Bl, K, bm, bn, tid);
        CP_COMMIT();
    }

    for (int c = 0; c < nc; ++c) {
        asm volatile("cp.async.wait_group %0;" :: "n"(NSTAGE - 2) : "memory");
        __syncthreads();
        int nx = c + NSTAGE - 1;
        if (nx < nc)
            load_stage(dyn + (nx % NSTAGE)*STAGEB, nx*64, Ah, Al, Bh, Bl, K, bm, bn, tid);
        CP_COMMIT();

        uint32_t sb = dyn + (c % NSTAGE)*STAGEB;
#pragma unroll
        for (int kk = 0; kk < 2; ++kk) {
            uint32_t chOff = (uint32_t)(kk*32 + lsel*16);
            uint32_t ah[2][4], al[2][4], bh[4][4], bl[4][4];
#pragma unroll
            for (int i = 0; i < 2; ++i) {
                uint32_t ro = (uint32_t)((wm + i*16 + lrow)*ROWB) + chOff;
                ldsm4(ah[i], sb + SB_AH + ro);
                ldsm4(al[i], sb + SB_AL + ro);
            }
#pragma unroll
            for (int j16 = 0; j16 < 4; ++j16) {
                uint32_t ro = (uint32_t)((wn + j16*16 + lrow)*ROWB) + chOff;
                ldsm4(bh[j16], sb + SB_BH + ro);
                ldsm4(bl[j16], sb + SB_BL + ro);
            }
#pragma unroll
            for (int i = 0; i < 2; ++i)
#pragma unroll
                for (int j = 0; j < 8; ++j) {
                    int j16 = j >> 1, hf = j & 1;
                    imma(acch[i][j], ah[i], bh[j16][hf], bh[j16][2 + hf]);
                    imma(accc[i][j], ah[i], bl[j16][hf], bl[j16][2 + hf]);
                    imma(accc[i][j], al[i], bh[j16][hf], bh[j16][2 + hf]);
                }
        }
        __syncthreads();
    }

    // epilogue: rescale and store fp32
    int qrow = lane >> 2;
    int qcol = (lane & 3) * 2;
    const float ks = 1.f/256.f;
#pragma unroll
    for (int i = 0; i < 2; ++i) {
        int r0 = bm + wm + i*16 + qrow;
        float sa0 = sA[r0], sa8 = sA[r0 + 8];
#pragma unroll
        for (int j = 0; j < 8; ++j) {
            int cc = bn + wn + j*8 + qcol;
            float sb0 = sB[cc], sb1 = sB[cc + 1];
            float f0 = ((float)acch[i][j][0] + (float)accc[i][j][0]*ks) * sa0 * sb0;
            float f1 = ((float)acch[i][j][1] + (float)accc[i][j][1]*ks) * sa0 * sb1;
            float f2 = ((float)acch[i][j][2] + (float)accc[i][j][2]*ks) * sa8 * sb0;
            float f3 = ((float)acch[i][j][3] + (float)accc[i][j][3]*ks) * sa8 * sb1;
            *(float2*)&U[(size_t)r0*Nld + cc]       = make_float2(f0, f1);
            *(float2*)&U[(size_t)(r0 + 8)*Nld + cc] = make_float2(f2, f3);
        }
    }
}

// ============================ SRU scan (-> fp32 h) ============================
__global__ void kscan(const float* __restrict__ U, float* __restrict__ hf,
                      const float* __restrict__ bfp, const float* __restrict__ brp) {
    int n   = blockIdx.x;
    int dir = blockIdx.y;
    int h   = threadIdx.x;
    int base = dir * (4*H_) + h;
    float bfv = bfp[dir*H_ + h];
    float brv = brp[dir*H_ + h];
    int l    = dir ? (L_ - 1) : 0;
    int step = dir ? -1 : 1;
    float c = 0.f;

    size_t ro = ((size_t)(l * N_ + n)) * (8*H_) + base;
    float z  = U[ro];
    float fv = U[ro + H_];
    float rv = U[ro + 2*H_];
    float hp = U[ro + 3*H_];

    for (int it = 0; it < L_; ++it) {
        int lcur = l;
        int lnext = l + step;
        float zn = 0.f, fn = 0.f, rn = 0.f, hpn = 0.f;
        if (it + 1 < L_) {
            size_t ro2 = ((size_t)(lnext * N_ + n)) * (8*H_) + base;
            zn  = U[ro2];
            fn  = U[ro2 + H_];
            rn  = U[ro2 + 2*H_];
            hpn = U[ro2 + 3*H_];
        }
        float ff = 1.f / (1.f + __expf(-(fv + bfv)));
        float rr = 1.f / (1.f + __expf(-(rv + brv)));
        c = ff * c + (1.f - ff) * z;
        float o = rr * c + (1.f - rr) * hp;
        hf[((size_t)(lcur * N_ + n)) * (2*H_) + dir*H_ + h] = o;
        z = zn; fv = fn; rv = rn; hp = hpn;
        l = lnext;
    }
}

// ============================ conv-transpose gather + residual ============================
#define TFO 16
__global__ void kfinal(const float* __restrict__ Y, const float* __restrict__ convb,
                       float* __restrict__ out) {
    __shared__ float sh[23 * 513];
    int n   = blockIdx.x;
    int fob = blockIdx.y * TFO;
    int tid = threadIdx.x;
    for (int i = tid; i < 23 * 512; i += 256) {
        int r = i >> 9, col = i & 511;
        int l = fob - 7 + r;
        float v = 0.f;
        if (l >= 0 && l < L_) v = Y[((size_t)(l * N_ + n)) * 512 + col];
        sh[r * 513 + col] = v;
    }
    __syncthreads();
    int fo_local = tid & 15;
    int cg = tid >> 4;
    int fo = fob + fo_local;
    int b = n >> 7, t = n & 127;
#pragma unroll
    for (int cc = 0; cc < 4; ++cc) {
        int c = cg * 4 + cc;
        float acc = convb[c];
#pragma unroll
        for (int k = 0; k < 8; ++k)
            acc += sh[(fo_local + 7 - k) * 513 + c * 8 + k];
        int oi = ((b*C_ + c)*T_ + t)*Fd_ + fo;
        out[oi] = acc + g_xn[oi];
    }
}

// ============================ launch ============================
extern "C" void kernel_launch(void* const* d_in, const int* in_sizes, int n_in,
                              void* d_out, int out_size) {
    const float* x     = (const float*)d_in[0];
    const float* gamma = (const float*)d_in[1];
    const float* beta  = (const float*)d_in[2];
    const float* W[4]  = {(const float*)d_in[3],  (const float*)d_in[6],
                          (const float*)d_in[9],  (const float*)d_in[12]};
    const float* bf[4] = {(const float*)d_in[4],  (const float*)d_in[7],
                          (const float*)d_in[10], (const float*)d_in[13]};
    const float* br[4] = {(const float*)d_in[5],  (const float*)d_in[8],
                          (const float*)d_in[11], (const float*)d_in[14]};
    const float* convW = (const float*)d_in[15];   // (2H, C, K) == (256, 512) row-major
    const float* convb = (const float*)d_in[16];
    float* out = (float*)d_out;

    void *pU, *paqh, *paql, *phf, *pwqh, *pwql, *psa, *psw;
    cudaGetSymbolAddress(&pU,   g_U);
    cudaGetSymbolAddress(&paqh, g_aqh);
    cudaGetSymbolAddress(&paql, g_aql);
    cudaGetSymbolAddress(&phf,  g_hf);
    cudaGetSymbolAddress(&pwqh, g_wqh);
    cudaGetSymbolAddress(&pwql, g_wql);
    cudaGetSymbolAddress(&psa,  g_sa);
    cudaGetSymbolAddress(&psw,  g_sw);
    int8_t* wqh = (int8_t*)pwqh;
    int8_t* wql = (int8_t*)pwql;
    float*  sw  = (float*)psw;
    const int woff[5] = {WOFF0, WOFF1, WOFF2, WOFF3, WOFFC};
    const int soff[5] = {SOFF0, SOFF1, SOFF2, SOFF3, SOFFC};

    cudaFuncSetAttribute(kgemm, cudaFuncAttributeMaxDynamicSharedMemorySize, GEMM_DSMEM);

    knorm<<<(B_*T_*Fd_ + 255)/256, 256>>>(x, gamma, beta);
    kunfold_q<<<M_, 128>>>();

    // transpose + quantize weights: W0 (512x1024), W1-3 (256x1024), convW (256x512)
    kwq<<<1024, 128>>>(W[0], wqh + woff[0], wql + woff[0], sw + soff[0], 512, 1024);
    for (int i = 1; i < 4; ++i)
        kwq<<<1024, 128>>>(W[i], wqh + woff[i], wql + woff[i], sw + soff[i], 256, 1024);
    kwq<<<512, 128>>>(convW, wqh + woff[4], wql + woff[4], sw + soff[4], 256, 512);

    // layer 0: A = h0q (M x 512), N = 1024
    kgemm<<<dim3(1024/128, M_/128), 256, GEMM_DSMEM>>>(
        (const int8_t*)paqh, (const int8_t*)paql,
        wqh + woff[0], wql + woff[0], (const float*)psa, sw + soff[0],
        (float*)pU, 512, 1024);
    kscan<<<dim3(N_, 2), 128>>>((const float*)pU, (float*)phf, bf[0], br[0]);
    kaq<<<M_, 64>>>();

    for (int i = 1; i < 4; ++i) {
        kgemm<<<dim3(1024/128, M_/128), 256, GEMM_DSMEM>>>(
            (const int8_t*)paqh, (const int8_t*)paql,
            wqh + woff[i], wql + woff[i], (const float*)psa, sw + soff[i],
            (float*)pU, 256, 1024);
        kscan<<<dim3(N_, 2), 128>>>((const float*)pU, (float*)phf, bf[i], br[i]);
        kaq<<<M_, 64>>>();
    }

    // conv-transpose as GEMM: Y (M x 512) = h (M x 256) @ convW^T-layout (512 x 256)
    kgemm<<<dim3(512/128, M_/128), 256, GEMM_DSMEM>>>(
        (const int8_t*)paqh, (const int8_t*)paql,
        wqh + woff[4], wql + woff[4], (const float*)psa, sw + soff[4],
        (float*)pU, 256, 512);
    kfinal<<<dim3(N_, Fd_/TFO), 256>>>((const float*)pU, convb, out);
}

// round 10
// speedup vs baseline: 2.4603x; 2.4603x over previous
#include <cuda_runtime.h>
#include <cuda_fp16.h>
#include <math.h>
#include <stdint.h>

#define B_  4
#define C_  64
#define T_  128
#define Fd_ 128
#define H_  128
#define K_  8
#define L_  121              // F - K + 1
#define N_  (B_*T_)          // 512
#define M_  (L_*N_)          // 61952
#define CK_ (C_*K_)          // 512

// weight scratch offsets (elements) for transposed fp16 weights [N][K]
#define WOFF0 0
#define WOFF1 (1024*512)
#define WOFF2 (WOFF1 + 1024*256)
#define WOFF3 (WOFF2 + 1024*256)
#define WOFFC (WOFF3 + 1024*256)
#define WTOT  (WOFFC + 512*256)

// ---- scratch (device globals; no allocation allowed) ----
__device__ float  g_xn [B_*C_*T_*Fd_];   // 16.8 MB  normed input (fp32, for residual)
__device__ __half g_h0h[M_*CK_];         // 63.4 MB  unfolded input hi
__device__ __half g_h0l[M_*CK_];         // 63.4 MB  unfolded input lo
__device__ __half g_hh [M_*2*H_];        // 31.7 MB  layer output hi
__device__ __half g_hl [M_*2*H_];        // 31.7 MB  layer output lo
__device__ __half g_U  [M_*8*H_];        // 126.9 MB GEMM output (fp16)
__device__ __half g_Wh [WTOT];           // transposed weights fp16

// ============================ helpers ============================
__device__ __forceinline__ uint32_t smem_u32(const void* p) {
    uint32_t a;
    asm("{ .reg .u64 t; cvta.to.shared.u64 t, %1; cvt.u32.u64 %0, t; }" : "=r"(a) : "l"(p));
    return a;
}
__device__ __forceinline__ void cp16(uint32_t s, const void* g) {
    asm volatile("cp.async.cg.shared.global [%0], [%1], 16;" :: "r"(s), "l"(g) : "memory");
}
#define CP_COMMIT() asm volatile("cp.async.commit_group;" ::: "memory")

__device__ __forceinline__ void ldsm4(uint32_t* r, uint32_t addr) {
    asm volatile("ldmatrix.sync.aligned.m8n8.x4.shared.b16 {%0,%1,%2,%3}, [%4];"
        : "=r"(r[0]), "=r"(r[1]), "=r"(r[2]), "=r"(r[3]) : "r"(addr));
}
__device__ __forceinline__ void hmma(float* c, const uint32_t* a, uint32_t b0, uint32_t b1) {
    asm volatile("mma.sync.aligned.m16n8k16.row.col.f32.f16.f16.f32 "
        "{%0,%1,%2,%3}, {%4,%5,%6,%7}, {%8,%9}, {%0,%1,%2,%3};"
        : "+f"(c[0]), "+f"(c[1]), "+f"(c[2]), "+f"(c[3])
        : "r"(a[0]), "r"(a[1]), "r"(a[2]), "r"(a[3]), "r"(b0), "r"(b1));
}

__device__ __forceinline__ void split_store(__half* ph, __half* pl, size_t idx, float v) {
    __half h = __float2half_rn(v);
    ph[idx] = h;
    pl[idx] = __float2half_rn(v - __half2float(h));
}

// ============================ channel norm ============================
__global__ void knorm(const float* __restrict__ x, const float* __restrict__ gamma,
                      const float* __restrict__ beta) {
    int idx = blockIdx.x * blockDim.x + threadIdx.x;   // over B*T*F
    if (idx >= B_*T_*Fd_) return;
    int f = idx % Fd_;
    int t = (idx / Fd_) % T_;
    int b = idx / (T_*Fd_);
    float v[C_];
    float s = 0.f;
#pragma unroll
    for (int c = 0; c < C_; ++c) {
        v[c] = x[((b*C_ + c)*T_ + t)*Fd_ + f];
        s += v[c];
    }
    float mu = s * (1.0f/C_);
    float vs = 0.f;
#pragma unroll
    for (int c = 0; c < C_; ++c) { float d = v[c]-mu; vs += d*d; }
    float inv = rsqrtf(vs*(1.0f/C_) + 1e-8f);
#pragma unroll
    for (int c = 0; c < C_; ++c) {
        g_xn[((b*C_ + c)*T_ + t)*Fd_ + f] = gamma[c]*(v[c]-mu)*inv + beta[c];
    }
}

// ============================ unfold (-> fp16 hi/lo) ============================
__global__ void kunfold() {
    int idx = blockIdx.x * blockDim.x + threadIdx.x;   // over M_*CK_
    if (idx >= M_*CK_) return;
    int ck = idx & 511;
    int m  = idx >> 9;
    int n  = m % N_;
    int l  = m / N_;
    int c  = ck >> 3, k = ck & 7;
    int b  = n >> 7, t = n & 127;
    float v = g_xn[((b*C_ + c)*T_ + t)*Fd_ + (l + k)];
    split_store(g_h0h, g_h0l, idx, v);
}

// ============ weight transpose to fp16: W (R x Cc) -> Wh[n][k] ============
__global__ void ktrans(const float* __restrict__ W, __half* __restrict__ wh,
                       int R, int Cc) {
    __shared__ float t[32][33];
    int c0 = blockIdx.x*32;
    int r0 = blockIdx.y*32;
    int tx = threadIdx.x, ty = threadIdx.y;
#pragma unroll
    for (int i = 0; i < 4; ++i)
        t[ty + i*8][tx] = W[(size_t)(r0 + ty + i*8)*Cc + c0 + tx];
    __syncthreads();
#pragma unroll
    for (int i = 0; i < 4; ++i) {
        int n = c0 + ty + i*8;
        int k = r0 + tx;
        wh[(size_t)n*R + k] = __float2half_rn(t[tx][ty + i*8]);
    }
}

// ============================ fp16 2-term GEMM ============================
// C(M x N) = A(M x K)*B(K x N) ~= Ah*Bh + Al*Bh.
// A hi/lo fp16 [M][K], B fp16 transposed [N][K].  CTA 256x128, warp 64x64, BK=32.
// SMEM stage: AH(256x80) | AL(256x80) | BH(128x80); rows 80B = 64B data + 16 pad.
#define ROWB   80
#define A_MATB (256*ROWB)          // 20480
#define B_MATB (128*ROWB)          // 10240
#define SB_AH  0
#define SB_AL  A_MATB
#define SB_BH  (2*A_MATB)
#define STAGEB (2*A_MATB + B_MATB)     // 51200
#define NSTAGE 3
#define GEMM_DSMEM (NSTAGE*STAGEB)     // 153600

__device__ __forceinline__ void load_stage(uint32_t sb, int k0,
    const __half* __restrict__ Ah, const __half* __restrict__ Al,
    const __half* __restrict__ Bh, int K, int bm, int bn, int tid) {
    // A: 256 rows x 4 chunks = 1024 cp16 for hi and lo -> 4 per thread each
#pragma unroll
    for (int i = tid; i < 1024; i += 256) {
        int row = i >> 2, ch = i & 3;
        uint32_t so = (uint32_t)(row*ROWB + ch*16);
        size_t ga = (size_t)(bm + row)*K + k0 + ch*8;
        cp16(sb + SB_AH + so, Ah + ga);
        cp16(sb + SB_AL + so, Al + ga);
    }
    // B: 128 rows x 4 chunks = 512 cp16 -> 2 per thread
#pragma unroll
    for (int i = tid; i < 512; i += 256) {
        int row = i >> 2, ch = i & 3;
        uint32_t so = (uint32_t)(row*ROWB + ch*16);
        size_t gb = (size_t)(bn + row)*K + k0 + ch*8;
        cp16(sb + SB_BH + so, Bh + gb);
    }
}

__global__ __launch_bounds__(256) void kgemm(
    const __half* __restrict__ Ah, const __half* __restrict__ Al,
    const __half* __restrict__ Bh,
    __half* __restrict__ U, int K, int Nld) {
    extern __shared__ char dsm[];
    uint32_t dyn = smem_u32(dsm);
    int tid  = threadIdx.x;
    int wid  = tid >> 5, lane = tid & 31;
    int bm   = blockIdx.y * 256, bn = blockIdx.x * 128;
    int wm   = (wid >> 1) * 64;        // warp m offset (0,64,128,192)
    int wn   = (wid & 1)  * 64;        // warp n offset (0,64)

    // per-lane ldmatrix row/chunk selectors
    int g = lane >> 3;
    int lrow = (g & 1) * 8 + (lane & 7);   // row within 16-row tile
    int lsel = g >> 1;                      // k-chunk half within k16

    float acc[4][8][4];
#pragma unroll
    for (int i = 0; i < 4; ++i)
#pragma unroll
        for (int j = 0; j < 8; ++j)
#pragma unroll
            for (int q = 0; q < 4; ++q) acc[i][j][q] = 0.f;

    int nc = K >> 5;                    // chunks of 32
#pragma unroll
    for (int s = 0; s < NSTAGE - 1; ++s) {
        load_stage(dyn + s*STAGEB, s*32, Ah, Al, Bh, K, bm, bn, tid);
        CP_COMMIT();
    }

    for (int c = 0; c < nc; ++c) {
        asm volatile("cp.async.wait_group %0;" :: "n"(NSTAGE - 2) : "memory");
        __syncthreads();
        int nx = c + NSTAGE - 1;
        if (nx < nc)
            load_stage(dyn + (nx % NSTAGE)*STAGEB, nx*32, Ah, Al, Bh, K, bm, bn, tid);
        CP_COMMIT();

        uint32_t sb = dyn + (c % NSTAGE)*STAGEB;
#pragma unroll
        for (int kk = 0; kk < 2; ++kk) {
            uint32_t chOff = (uint32_t)((kk*2 + lsel)*16);
            uint32_t ah[4][4], al[4][4], bh[4][4];
#pragma unroll
            for (int i = 0; i < 4; ++i) {
                uint32_t ro = (uint32_t)((wm + i*16 + lrow)*ROWB) + chOff;
                ldsm4(ah[i], sb + SB_AH + ro);
                ldsm4(al[i], sb + SB_AL + ro);
            }
#pragma unroll
            for (int j16 = 0; j16 < 4; ++j16) {
                uint32_t ro = (uint32_t)((wn + j16*16 + lrow)*ROWB) + chOff;
                ldsm4(bh[j16], sb + SB_BH + ro);
            }
#pragma unroll
            for (int i = 0; i < 4; ++i)
#pragma unroll
                for (int j = 0; j < 8; ++j) {
                    int j16 = j >> 1, hf = j & 1;
                    hmma(acc[i][j], ah[i], bh[j16][hf], bh[j16][2 + hf]);
                    hmma(acc[i][j], al[i], bh[j16][hf], bh[j16][2 + hf]);
                }
        }
        __syncthreads();
    }

    // epilogue: pack fp16, store half2
    int qrow = lane >> 2;
    int qcol = (lane & 3) * 2;
#pragma unroll
    for (int i = 0; i < 4; ++i) {
        int r0 = bm + wm + i*16 + qrow;
#pragma unroll
        for (int j = 0; j < 8; ++j) {
            int cc = bn + wn + j*8 + qcol;
            *(__half2*)&U[(size_t)r0*Nld + cc] =
                __floats2half2_rn(acc[i][j][0], acc[i][j][1]);
            *(__half2*)&U[(size_t)(r0 + 8)*Nld + cc] =
                __floats2half2_rn(acc[i][j][2], acc[i][j][3]);
        }
    }
}

// ============================ SRU scan (fp16 U -> fp16 hi/lo h) ============================
__global__ void kscan(const __half* __restrict__ U,
                      __half* __restrict__ hh, __half* __restrict__ hl,
                      const float* __restrict__ bfp, const float* __restrict__ brp) {
    int n   = blockIdx.x;
    int dir = blockIdx.y;
    int h   = threadIdx.x;
    int base = dir * (4*H_) + h;
    float bfv = bfp[dir*H_ + h];
    float brv = brp[dir*H_ + h];
    int l    = dir ? (L_ - 1) : 0;
    int step = dir ? -1 : 1;
    float c = 0.f;

    size_t ro = ((size_t)(l * N_ + n)) * (8*H_) + base;
    float z  = __half2float(U[ro]);
    float fv = __half2float(U[ro + H_]);
    float rv = __half2float(U[ro + 2*H_]);
    float hp = __half2float(U[ro + 3*H_]);

    for (int it = 0; it < L_; ++it) {
        int lcur = l;
        int lnext = l + step;
        float zn = 0.f, fn = 0.f, rn = 0.f, hpn = 0.f;
        if (it + 1 < L_) {
            size_t ro2 = ((size_t)(lnext * N_ + n)) * (8*H_) + base;
            zn  = __half2float(U[ro2]);
            fn  = __half2float(U[ro2 + H_]);
            rn  = __half2float(U[ro2 + 2*H_]);
            hpn = __half2float(U[ro2 + 3*H_]);
        }
        float ff = 1.f / (1.f + __expf(-(fv + bfv)));
        float rr = 1.f / (1.f + __expf(-(rv + brv)));
        c = ff * c + (1.f - ff) * z;
        float o = rr * c + (1.f - rr) * hp;
        split_store(hh, hl, ((size_t)(lcur * N_ + n)) * (2*H_) + dir*H_ + h, o);
        z = zn; fv = fn; rv = rn; hp = hpn;
        l = lnext;
    }
}

// ============================ conv-transpose gather + residual ============================
#define TFO 16
__global__ void kfinal(const __half* __restrict__ Y, const float* __restrict__ convb,
                       float* __restrict__ out) {
    __shared__ float sh[23 * 513];
    int n   = blockIdx.x;
    int fob = blockIdx.y * TFO;
    int tid = threadIdx.x;
    for (int i = tid; i < 23 * 512; i += 256) {
        int r = i >> 9, col = i & 511;
        int l = fob - 7 + r;
        float v = 0.f;
        if (l >= 0 && l < L_) v = __half2float(Y[((size_t)(l * N_ + n)) * 512 + col]);
        sh[r * 513 + col] = v;
    }
    __syncthreads();
    int fo_local = tid & 15;
    int cg = tid >> 4;
    int fo = fob + fo_local;
    int b = n >> 7, t = n & 127;
#pragma unroll
    for (int cc = 0; cc < 4; ++cc) {
        int c = cg * 4 + cc;
        float acc = convb[c];
#pragma unroll
        for (int k = 0; k < 8; ++k)
            acc += sh[(fo_local + 7 - k) * 513 + c * 8 + k];
        int oi = ((b*C_ + c)*T_ + t)*Fd_ + fo;
        out[oi] = acc + g_xn[oi];
    }
}

// ============================ launch ============================
extern "C" void kernel_launch(void* const* d_in, const int* in_sizes, int n_in,
                              void* d_out, int out_size) {
    const float* x     = (const float*)d_in[0];
    const float* gamma = (const float*)d_in[1];
    const float* beta  = (const float*)d_in[2];
    const float* W[4]  = {(const float*)d_in[3],  (const float*)d_in[6],
                          (const float*)d_in[9],  (const float*)d_in[12]};
    const float* bf[4] = {(const float*)d_in[4],  (const float*)d_in[7],
                          (const float*)d_in[10], (const float*)d_in[13]};
    const float* br[4] = {(const float*)d_in[5],  (const float*)d_in[8],
                          (const float*)d_in[11], (const float*)d_in[14]};
    const float* convW = (const float*)d_in[15];   // (2H, C, K) == (256, 512) row-major
    const float* convb = (const float*)d_in[16];
    float* out = (float*)d_out;

    void *pU, *ph0h, *ph0l, *phh, *phl, *pwh;
    cudaGetSymbolAddress(&pU,   g_U);
    cudaGetSymbolAddress(&ph0h, g_h0h);
    cudaGetSymbolAddress(&ph0l, g_h0l);
    cudaGetSymbolAddress(&phh,  g_hh);
    cudaGetSymbolAddress(&phl,  g_hl);
    cudaGetSymbolAddress(&pwh,  g_Wh);
    __half* Wh = (__half*)pwh;
    const int woff[5] = {WOFF0, WOFF1, WOFF2, WOFF3, WOFFC};

    cudaFuncSetAttribute(kgemm, cudaFuncAttributeMaxDynamicSharedMemorySize, GEMM_DSMEM);

    knorm<<<(B_*T_*Fd_ + 255)/256, 256>>>(x, gamma, beta);
    kunfold<<<(M_*CK_ + 255)/256, 256>>>();

    // transpose weights: W0 (512x1024), W1-3 (256x1024), convW (256x512)
    ktrans<<<dim3(1024/32, 512/32), dim3(32,8)>>>(W[0], Wh + woff[0], 512, 1024);
    for (int i = 1; i < 4; ++i)
        ktrans<<<dim3(1024/32, 256/32), dim3(32,8)>>>(W[i], Wh + woff[i], 256, 1024);
    ktrans<<<dim3(512/32, 256/32), dim3(32,8)>>>(convW, Wh + woff[4], 256, 512);

    // layer 0: A = h0 (M x 512), N = 1024
    kgemm<<<dim3(1024/128, M_/256), 256, GEMM_DSMEM>>>(
        (const __half*)ph0h, (const __half*)ph0l, Wh + woff[0],
        (__half*)pU, 512, 1024);
    kscan<<<dim3(N_, 2), 128>>>((const __half*)pU, (__half*)phh, (__half*)phl,
                                bf[0], br[0]);

    for (int i = 1; i < 4; ++i) {
        kgemm<<<dim3(1024/128, M_/256), 256, GEMM_DSMEM>>>(
            (const __half*)phh, (const __half*)phl, Wh + woff[i],
            (__half*)pU, 256, 1024);
        kscan<<<dim3(N_, 2), 128>>>((const __half*)pU, (__half*)phh, (__half*)phl,
                                    bf[i], br[i]);
    }

    // conv-transpose as GEMM: Y (M x 512) = h (M x 256) @ convW^T-layout (512 x 256)
    kgemm<<<dim3(512/128, M_/256), 256, GEMM_DSMEM>>>(
        (const __half*)phh, (const __half*)phl, Wh + woff[4],
        (__half*)pU, 256, 512);
    kfinal<<<dim3(N_, Fd_/TFO), 256>>>((const __half*)pU, convb, out);
}

// round 13
// speedup vs baseline: 3.6758x; 1.4940x over previous
#include <cuda_runtime.h>
#include <cuda_fp16.h>
#include <math.h>
#include <stdint.h>

#define B_  4
#define C_  64
#define T_  128
#define Fd_ 128
#define H_  128
#define K_  8
#define L_  121              // F - K + 1
#define N_  (B_*T_)          // 512
#define M_  (L_*N_)          // 61952
#define CK_ (C_*K_)          // 512

// weight scratch offsets (elements) for transposed fp16 weights [N][K]
#define WOFF0 0
#define WOFF1 (1024*512)
#define WOFF2 (WOFF1 + 1024*256)
#define WOFF3 (WOFF2 + 1024*256)
#define WOFFC (WOFF3 + 1024*256)
#define WTOT  (WOFFC + 512*256)

// ---- scratch (device globals; no allocation allowed) ----
__device__ float  g_xn [B_*C_*T_*Fd_];   // 16.8 MB  normed input (fp32, for residual)
__device__ __half g_h0 [M_*CK_];         // 63.4 MB  unfolded input fp16
__device__ __half g_h  [M_*2*H_];        // 31.7 MB  layer output fp16
__device__ __half g_U  [M_*8*H_];        // 126.9 MB GEMM output (fp16)
__device__ __half g_Wh [WTOT];           // transposed weights fp16

// ============================ helpers ============================
__device__ __forceinline__ uint32_t smem_u32(const void* p) {
    uint32_t a;
    asm("{ .reg .u64 t; cvta.to.shared.u64 t, %1; cvt.u32.u64 %0, t; }" : "=r"(a) : "l"(p));
    return a;
}
__device__ __forceinline__ void cp16(uint32_t s, const void* g) {
    asm volatile("cp.async.cg.shared.global [%0], [%1], 16;" :: "r"(s), "l"(g) : "memory");
}
#define CP_COMMIT() asm volatile("cp.async.commit_group;" ::: "memory")

__device__ __forceinline__ void ldsm4(uint32_t* r, uint32_t addr) {
    asm volatile("ldmatrix.sync.aligned.m8n8.x4.shared.b16 {%0,%1,%2,%3}, [%4];"
        : "=r"(r[0]), "=r"(r[1]), "=r"(r[2]), "=r"(r[3]) : "r"(addr));
}
__device__ __forceinline__ void hmma(float* c, const uint32_t* a, uint32_t b0, uint32_t b1) {
    asm volatile("mma.sync.aligned.m16n8k16.row.col.f32.f16.f16.f32 "
        "{%0,%1,%2,%3}, {%4,%5,%6,%7}, {%8,%9}, {%0,%1,%2,%3};"
        : "+f"(c[0]), "+f"(c[1]), "+f"(c[2]), "+f"(c[3])
        : "r"(a[0]), "r"(a[1]), "r"(a[2]), "r"(a[3]), "r"(b0), "r"(b1));
}

// ============================ channel norm ============================
__global__ void knorm(const float* __restrict__ x, const float* __restrict__ gamma,
                      const float* __restrict__ beta) {
    int idx = blockIdx.x * blockDim.x + threadIdx.x;   // over B*T*F
    if (idx >= B_*T_*Fd_) return;
    int f = idx % Fd_;
    int t = (idx / Fd_) % T_;
    int b = idx / (T_*Fd_);
    float v[C_];
    float s = 0.f;
#pragma unroll
    for (int c = 0; c < C_; ++c) {
        v[c] = x[((b*C_ + c)*T_ + t)*Fd_ + f];
        s += v[c];
    }
    float mu = s * (1.0f/C_);
    float vs = 0.f;
#pragma unroll
    for (int c = 0; c < C_; ++c) { float d = v[c]-mu; vs += d*d; }
    float inv = rsqrtf(vs*(1.0f/C_) + 1e-8f);
#pragma unroll
    for (int c = 0; c < C_; ++c) {
        g_xn[((b*C_ + c)*T_ + t)*Fd_ + f] = gamma[c]*(v[c]-mu)*inv + beta[c];
    }
}

// ============================ unfold (-> fp16) ============================
__global__ void kunfold() {
    int idx = blockIdx.x * blockDim.x + threadIdx.x;   // over M_*CK_
    if (idx >= M_*CK_) return;
    int ck = idx & 511;
    int m  = idx >> 9;
    int n  = m % N_;
    int l  = m / N_;
    int c  = ck >> 3, k = ck & 7;
    int b  = n >> 7, t = n & 127;
    g_h0[idx] = __float2half_rn(g_xn[((b*C_ + c)*T_ + t)*Fd_ + (l + k)]);
}

// ============ weight transpose to fp16: W (R x Cc) -> Wh[n][k] ============
__global__ void ktrans(const float* __restrict__ W, __half* __restrict__ wh,
                       int R, int Cc) {
    __shared__ float t[32][33];
    int c0 = blockIdx.x*32;
    int r0 = blockIdx.y*32;
    int tx = threadIdx.x, ty = threadIdx.y;
#pragma unroll
    for (int i = 0; i < 4; ++i)
        t[ty + i*8][tx] = W[(size_t)(r0 + ty + i*8)*Cc + c0 + tx];
    __syncthreads();
#pragma unroll
    for (int i = 0; i < 4; ++i) {
        int n = c0 + ty + i*8;
        int k = r0 + tx;
        wh[(size_t)n*R + k] = __float2half_rn(t[tx][ty + i*8]);
    }
}

// ============================ fp16 GEMM ============================
// C(M x N) = A(M x K)*B(K x N); A fp16 [M][K], B fp16 transposed [N][K].
// CTA 256x128, warp 64x64, BK=32, 4-stage cp.async pipeline.
// SMEM stage: A(256x80) | B(128x80); rows 80B = 64B data + 16 pad.
#define ROWB   80
#define A_MATB (256*ROWB)          // 20480
#define B_MATB (128*ROWB)          // 10240
#define SB_A   0
#define SB_B   A_MATB
#define STAGEB (A_MATB + B_MATB)       // 30720
#define NSTAGE 4
#define GEMM_DSMEM (NSTAGE*STAGEB)     // 122880

__device__ __forceinline__ void load_stage(uint32_t sb, int k0,
    const __half* __restrict__ A, const __half* __restrict__ Bh,
    int K, int bm, int bn, int tid) {
    // A: 256 rows x 4 chunks = 1024 cp16 -> 4 per thread
#pragma unroll
    for (int i = tid; i < 1024; i += 256) {
        int row = i >> 2, ch = i & 3;
        uint32_t so = (uint32_t)(row*ROWB + ch*16);
        cp16(sb + SB_A + so, A + (size_t)(bm + row)*K + k0 + ch*8);
    }
    // B: 128 rows x 4 chunks = 512 cp16 -> 2 per thread
#pragma unroll
    for (int i = tid; i < 512; i += 256) {
        int row = i >> 2, ch = i & 3;
        uint32_t so = (uint32_t)(row*ROWB + ch*16);
        cp16(sb + SB_B + so, Bh + (size_t)(bn + row)*K + k0 + ch*8);
    }
}

__global__ __launch_bounds__(256) void kgemm(
    const __half* __restrict__ A, const __half* __restrict__ Bh,
    __half* __restrict__ U, int K, int Nld) {
    extern __shared__ char dsm[];
    uint32_t dyn = smem_u32(dsm);
    int tid  = threadIdx.x;
    int wid  = tid >> 5, lane = tid & 31;
    int bm   = blockIdx.y * 256, bn = blockIdx.x * 128;
    int wm   = (wid >> 1) * 64;        // warp m offset (0,64,128,192)
    int wn   = (wid & 1)  * 64;        // warp n offset (0,64)

    // per-lane ldmatrix row/chunk selectors
    int g = lane >> 3;
    int lrow = (g & 1) * 8 + (lane & 7);   // row within 16-row tile
    int lsel = g >> 1;                      // k-chunk half within k16

    float acc[4][8][4];
#pragma unroll
    for (int i = 0; i < 4; ++i)
#pragma unroll
        for (int j = 0; j < 8; ++j)
#pragma unroll
            for (int q = 0; q < 4; ++q) acc[i][j][q] = 0.f;

    int nc = K >> 5;                    // chunks of 32
#pragma unroll
    for (int s = 0; s < NSTAGE - 1; ++s) {
        if (s < nc) load_stage(dyn + s*STAGEB, s*32, A, Bh, K, bm, bn, tid);
        CP_COMMIT();
    }

    for (int c = 0; c < nc; ++c) {
        asm volatile("cp.async.wait_group %0;" :: "n"(NSTAGE - 2) : "memory");
        __syncthreads();
        int nx = c + NSTAGE - 1;
        if (nx < nc)
            load_stage(dyn + (nx % NSTAGE)*STAGEB, nx*32, A, Bh, K, bm, bn, tid);
        CP_COMMIT();

        uint32_t sb = dyn + (c % NSTAGE)*STAGEB;
#pragma unroll
        for (int kk = 0; kk < 2; ++kk) {
            uint32_t chOff = (uint32_t)((kk*2 + lsel)*16);
            uint32_t ah[4][4], bh[4][4];
#pragma unroll
            for (int i = 0; i < 4; ++i) {
                uint32_t ro = (uint32_t)((wm + i*16 + lrow)*ROWB) + chOff;
                ldsm4(ah[i], sb + SB_A + ro);
            }
#pragma unroll
            for (int j16 = 0; j16 < 4; ++j16) {
                uint32_t ro = (uint32_t)((wn + j16*16 + lrow)*ROWB) + chOff;
                ldsm4(bh[j16], sb + SB_B + ro);
            }
#pragma unroll
            for (int i = 0; i < 4; ++i)
#pragma unroll
                for (int j = 0; j < 8; ++j) {
                    int j16 = j >> 1, hf = j & 1;
                    hmma(acc[i][j], ah[i], bh[j16][hf], bh[j16][2 + hf]);
                }
        }
        __syncthreads();
    }

    // epilogue: pack fp16, store half2
    int qrow = lane >> 2;
    int qcol = (lane & 3) * 2;
#pragma unroll
    for (int i = 0; i < 4; ++i) {
        int r0 = bm + wm + i*16 + qrow;
#pragma unroll
        for (int j = 0; j < 8; ++j) {
            int cc = bn + wn + j*8 + qcol;
            *(__half2*)&U[(size_t)r0*Nld + cc] =
                __floats2half2_rn(acc[i][j][0], acc[i][j][1]);
            *(__half2*)&U[(size_t)(r0 + 8)*Nld + cc] =
                __floats2half2_rn(acc[i][j][2], acc[i][j][3]);
        }
    }
}

// ============================ SRU scan (fp16 U -> fp16 h) ============================
__global__ void kscan(const __half* __restrict__ U, __half* __restrict__ hout,
                      const float* __restrict__ bfp, const float* __restrict__ brp) {
    int n   = blockIdx.x;
    int dir = blockIdx.y;
    int h   = threadIdx.x;
    int base = dir * (4*H_) + h;
    float bfv = bfp[dir*H_ + h];
    float brv = brp[dir*H_ + h];
    int l    = dir ? (L_ - 1) : 0;
    int step = dir ? -1 : 1;
    float c = 0.f;

    size_t ro = ((size_t)(l * N_ + n)) * (8*H_) + base;
    float z  = __half2float(U[ro]);
    float fv = __half2float(U[ro + H_]);
    float rv = __half2float(U[ro + 2*H_]);
    float hp = __half2float(U[ro + 3*H_]);

    for (int it = 0; it < L_; ++it) {
        int lcur = l;
        int lnext = l + step;
        float zn = 0.f, fn = 0.f, rn = 0.f, hpn = 0.f;
        if (it + 1 < L_) {
            size_t ro2 = ((size_t)(lnext * N_ + n)) * (8*H_) + base;
            zn  = __half2float(U[ro2]);
            fn  = __half2float(U[ro2 + H_]);
            rn  = __half2float(U[ro2 + 2*H_]);
            hpn = __half2float(U[ro2 + 3*H_]);
        }
        float ff = 1.f / (1.f + __expf(-(fv + bfv)));
        float rr = 1.f / (1.f + __expf(-(rv + brv)));
        c = ff * c + (1.f - ff) * z;
        float o = rr * c + (1.f - rr) * hp;
        hout[((size_t)(lcur * N_ + n)) * (2*H_) + dir*H_ + h] = __float2half_rn(o);
        z = zn; fv = fn; rv = rn; hp = hpn;
        l = lnext;
    }
}

// ============================ conv-transpose gather + residual ============================
#define TFO 16
__global__ void kfinal(const __half* __restrict__ Y, const float* __restrict__ convb,
                       float* __restrict__ out) {
    __shared__ float sh[23 * 513];
    int n   = blockIdx.x;
    int fob = blockIdx.y * TFO;
    int tid = threadIdx.x;
    for (int i = tid; i < 23 * 512; i += 256) {
        int r = i >> 9, col = i & 511;
        int l = fob - 7 + r;
        float v = 0.f;
        if (l >= 0 && l < L_) v = __half2float(Y[((size_t)(l * N_ + n)) * 512 + col]);
        sh[r * 513 + col] = v;
    }
    __syncthreads();
    int fo_local = tid & 15;
    int cg = tid >> 4;
    int fo = fob + fo_local;
    int b = n >> 7, t = n & 127;
#pragma unroll
    for (int cc = 0; cc < 4; ++cc) {
        int c = cg * 4 + cc;
        float acc = convb[c];
#pragma unroll
        for (int k = 0; k < 8; ++k)
            acc += sh[(fo_local + 7 - k) * 513 + c * 8 + k];
        int oi = ((b*C_ + c)*T_ + t)*Fd_ + fo;
        out[oi] = acc + g_xn[oi];
    }
}

// ============================ launch ============================
extern "C" void kernel_launch(void* const* d_in, const int* in_sizes, int n_in,
                              void* d_out, int out_size) {
    const float* x     = (const float*)d_in[0];
    const float* gamma = (const float*)d_in[1];
    const float* beta  = (const float*)d_in[2];
    const float* W[4]  = {(const float*)d_in[3],  (const float*)d_in[6],
                          (const float*)d_in[9],  (const float*)d_in[12]};
    const float* bf[4] = {(const float*)d_in[4],  (const float*)d_in[7],
                          (const float*)d_in[10], (const float*)d_in[13]};
    const float* br[4] = {(const float*)d_in[5],  (const float*)d_in[8],
                          (const float*)d_in[11], (const float*)d_in[14]};
    const float* convW = (const float*)d_in[15];   // (2H, C, K) == (256, 512) row-major
    const float* convb = (const float*)d_in[16];
    float* out = (float*)d_out;

    void *pU, *ph0, *ph, *pwh;
    cudaGetSymbolAddress(&pU,  g_U);
    cudaGetSymbolAddress(&ph0, g_h0);
    cudaGetSymbolAddress(&ph,  g_h);
    cudaGetSymbolAddress(&pwh, g_Wh);
    __half* Wh = (__half*)pwh;
    const int woff[5] = {WOFF0, WOFF1, WOFF2, WOFF3, WOFFC};

    cudaFuncSetAttribute(kgemm, cudaFuncAttributeMaxDynamicSharedMemorySize, GEMM_DSMEM);

    knorm<<<(B_*T_*Fd_ + 255)/256, 256>>>(x, gamma, beta);
    kunfold<<<(M_*CK_ + 255)/256, 256>>>();

    // transpose weights: W0 (512x1024), W1-3 (256x1024), convW (256x512)
    ktrans<<<dim3(1024/32, 512/32), dim3(32,8)>>>(W[0], Wh + woff[0], 512, 1024);
    for (int i = 1; i < 4; ++i)
        ktrans<<<dim3(1024/32, 256/32), dim3(32,8)>>>(W[i], Wh + woff[i], 256, 1024);
    ktrans<<<dim3(512/32, 256/32), dim3(32,8)>>>(convW, Wh + woff[4], 256, 512);

    // layer 0: A = h0 (M x 512), N = 1024
    kgemm<<<dim3(1024/128, M_/256), 256, GEMM_DSMEM>>>(
        (const __half*)ph0, Wh + woff[0], (__half*)pU, 512, 1024);
    kscan<<<dim3(N_, 2), 128>>>((const __half*)pU, (__half*)ph, bf[0], br[0]);

    for (int i = 1; i < 4; ++i) {
        kgemm<<<dim3(1024/128, M_/256), 256, GEMM_DSMEM>>>(
            (const __half*)ph, Wh + woff[i], (__half*)pU, 256, 1024);
        kscan<<<dim3(N_, 2), 128>>>((const __half*)pU, (__half*)ph, bf[i], br[i]);
    }

    // conv-transpose as GEMM: Y (M x 512) = h (M x 256) @ convW^T-layout (512 x 256)
    kgemm<<<dim3(512/128, M_/256), 256, GEMM_DSMEM>>>(
        (const __half*)ph, Wh + woff[4], (__half*)pU, 256, 512);
    kfinal<<<dim3(N_, Fd_/TFO), 256>>>((const __half*)pU, convb, out);
}

// round 14
// speedup vs baseline: 3.9040x; 1.0621x over previous
#include <cuda_runtime.h>
#include <cuda_fp16.h>
#include <math.h>
#include <stdint.h>

#define B_  4
#define C_  64
#define T_  128
#define Fd_ 128
#define H_  128
#define K_  8
#define L_  121              // F - K + 1
#define N_  (B_*T_)          // 512
#define M_  (L_*N_)          // 61952
#define CK_ (C_*K_)          // 512

// weight scratch offsets (elements) for transposed fp16 weights
#define WOFF0 0
#define WOFF1 (1024*512)
#define WOFF2 (WOFF1 + 1024*256)
#define WOFF3 (WOFF2 + 1024*256)
#define WOFFC (WOFF3 + 1024*256)
#define WTOT  (WOFFC + 512*256)

// ---- scratch (device globals; no allocation allowed) ----
__device__ float  g_xn [B_*C_*T_*Fd_];   // 16.8 MB  normed input (fp32, for residual)
__device__ __half g_X  [Fd_*N_*C_];      //  8.4 MB  normed input fp16, layout [(f*512+n)*64+c]
__device__ __half g_h  [M_*2*H_];        // 31.7 MB  layer output fp16
__device__ __half g_U  [M_*8*H_];        // 126.9 MB GEMM output (fp16)
__device__ __half g_Wh [WTOT];           // transposed weights fp16

// ============================ helpers ============================
__device__ __forceinline__ uint32_t smem_u32(const void* p) {
    uint32_t a;
    asm("{ .reg .u64 t; cvta.to.shared.u64 t, %1; cvt.u32.u64 %0, t; }" : "=r"(a) : "l"(p));
    return a;
}
__device__ __forceinline__ void cp16(uint32_t s, const void* g) {
    asm volatile("cp.async.cg.shared.global [%0], [%1], 16;" :: "r"(s), "l"(g) : "memory");
}
#define CP_COMMIT() asm volatile("cp.async.commit_group;" ::: "memory")

__device__ __forceinline__ void ldsm4(uint32_t* r, uint32_t addr) {
    asm volatile("ldmatrix.sync.aligned.m8n8.x4.shared.b16 {%0,%1,%2,%3}, [%4];"
        : "=r"(r[0]), "=r"(r[1]), "=r"(r[2]), "=r"(r[3]) : "r"(addr));
}
__device__ __forceinline__ void hmma(float* c, const uint32_t* a, uint32_t b0, uint32_t b1) {
    asm volatile("mma.sync.aligned.m16n8k16.row.col.f32.f16.f16.f32 "
        "{%0,%1,%2,%3}, {%4,%5,%6,%7}, {%8,%9}, {%0,%1,%2,%3};"
        : "+f"(c[0]), "+f"(c[1]), "+f"(c[2]), "+f"(c[3])
        : "r"(a[0]), "r"(a[1]), "r"(a[2]), "r"(a[3]), "r"(b0), "r"(b1));
}

// ============================ channel norm (+ fp16 X side output) ============================
__global__ void knorm(const float* __restrict__ x, const float* __restrict__ gamma,
                      const float* __restrict__ beta) {
    int idx = blockIdx.x * blockDim.x + threadIdx.x;   // over B*T*F
    if (idx >= B_*T_*Fd_) return;
    int f = idx % Fd_;
    int t = (idx / Fd_) % T_;
    int b = idx / (T_*Fd_);
    int n = b*T_ + t;
    float v[C_];
    float s = 0.f;
#pragma unroll
    for (int c = 0; c < C_; ++c) {
        v[c] = x[((b*C_ + c)*T_ + t)*Fd_ + f];
        s += v[c];
    }
    float mu = s * (1.0f/C_);
    float vs = 0.f;
#pragma unroll
    for (int c = 0; c < C_; ++c) { float d = v[c]-mu; vs += d*d; }
    float inv = rsqrtf(vs*(1.0f/C_) + 1e-8f);
    __half hx[C_];
#pragma unroll
    for (int c = 0; c < C_; ++c) {
        float o = gamma[c]*(v[c]-mu)*inv + beta[c];
        g_xn[((b*C_ + c)*T_ + t)*Fd_ + f] = o;
        hx[c] = __float2half_rn(o);
    }
    // X layout: [(f*512 + n)*64 + c], 128B contiguous per (f,n)
    uint4* dst = (uint4*)&g_X[((size_t)f*N_ + n)*C_];
    const uint4* src = (const uint4*)hx;
#pragma unroll
    for (int q = 0; q < 8; ++q) dst[q] = src[q];
}

// ============ weight transpose to fp16: W (R x Cc) -> Wh[n][k] ============
__global__ void ktrans(const float* __restrict__ W, __half* __restrict__ wh,
                       int R, int Cc) {
    __shared__ float t[32][33];
    int c0 = blockIdx.x*32;
    int r0 = blockIdx.y*32;
    int tx = threadIdx.x, ty = threadIdx.y;
#pragma unroll
    for (int i = 0; i < 4; ++i)
        t[ty + i*8][tx] = W[(size_t)(r0 + ty + i*8)*Cc + c0 + tx];
    __syncthreads();
#pragma unroll
    for (int i = 0; i < 4; ++i) {
        int n = c0 + ty + i*8;
        int k = r0 + tx;
        wh[(size_t)n*R + k] = __float2half_rn(t[tx][ty + i*8]);
    }
}

// ============ layer-0 weight transpose with k-major permute ============
// Wt0[j][k*64 + c] = W0[c*8 + k][j]   (512 rows ck, 1024 cols j)
__global__ void ktrans0(const float* __restrict__ W, __half* __restrict__ wt) {
    __shared__ float t[32][33];
    int c0 = blockIdx.x*32;            // over j (1024)
    int r0 = blockIdx.y*32;            // over ck (512)
    int tx = threadIdx.x, ty = threadIdx.y;
#pragma unroll
    for (int i = 0; i < 4; ++i)
        t[ty + i*8][tx] = W[(size_t)(r0 + ty + i*8)*1024 + c0 + tx];
    __syncthreads();
#pragma unroll
    for (int i = 0; i < 4; ++i) {
        int j  = c0 + ty + i*8;
        int ck = r0 + tx;
        int c = ck >> 3, k = ck & 7;
        wt[(size_t)j*512 + k*64 + c] = __float2half_rn(t[tx][ty + i*8]);
    }
}

// ============================ generic fp16 GEMM (layers 1-3, conv) ============================
// C(M x N) = A(M x K)*B(K x N); A fp16 [M][K], B fp16 transposed [N][K].
// CTA 256x128, warp 64x64, BK=32, 4-stage cp.async pipeline.
#define ROWB   80
#define A_MATB (256*ROWB)
#define B_MATB (128*ROWB)
#define SB_A   0
#define SB_B   A_MATB
#define STAGEB (A_MATB + B_MATB)       // 30720
#define NSTAGE 4
#define GEMM_DSMEM (NSTAGE*STAGEB)     // 122880

__device__ __forceinline__ void load_stage(uint32_t sb, int k0,
    const __half* __restrict__ A, const __half* __restrict__ Bh,
    int K, int bm, int bn, int tid) {
#pragma unroll
    for (int i = tid; i < 1024; i += 256) {
        int row = i >> 2, ch = i & 3;
        uint32_t so = (uint32_t)(row*ROWB + ch*16);
        cp16(sb + SB_A + so, A + (size_t)(bm + row)*K + k0 + ch*8);
    }
#pragma unroll
    for (int i = tid; i < 512; i += 256) {
        int row = i >> 2, ch = i & 3;
        uint32_t so = (uint32_t)(row*ROWB + ch*16);
        cp16(sb + SB_B + so, Bh + (size_t)(bn + row)*K + k0 + ch*8);
    }
}

__global__ __launch_bounds__(256) void kgemm(
    const __half* __restrict__ A, const __half* __restrict__ Bh,
    __half* __restrict__ U, int K, int Nld) {
    extern __shared__ char dsm[];
    uint32_t dyn = smem_u32(dsm);
    int tid  = threadIdx.x;
    int wid  = tid >> 5, lane = tid & 31;
    int bm   = blockIdx.y * 256, bn = blockIdx.x * 128;
    int wm   = (wid >> 1) * 64;
    int wn   = (wid & 1)  * 64;

    int g = lane >> 3;
    int lrow = (g & 1) * 8 + (lane & 7);
    int lsel = g >> 1;

    float acc[4][8][4];
#pragma unroll
    for (int i = 0; i < 4; ++i)
#pragma unroll
        for (int j = 0; j < 8; ++j)
#pragma unroll
            for (int q = 0; q < 4; ++q) acc[i][j][q] = 0.f;

    int nc = K >> 5;
#pragma unroll
    for (int s = 0; s < NSTAGE - 1; ++s) {
        if (s < nc) load_stage(dyn + s*STAGEB, s*32, A, Bh, K, bm, bn, tid);
        CP_COMMIT();
    }

    for (int c = 0; c < nc; ++c) {
        asm volatile("cp.async.wait_group %0;" :: "n"(NSTAGE - 2) : "memory");
        __syncthreads();
        int nx = c + NSTAGE - 1;
        if (nx < nc)
            load_stage(dyn + (nx % NSTAGE)*STAGEB, nx*32, A, Bh, K, bm, bn, tid);
        CP_COMMIT();

        uint32_t sb = dyn + (c % NSTAGE)*STAGEB;
#pragma unroll
        for (int kk = 0; kk < 2; ++kk) {
            uint32_t chOff = (uint32_t)((kk*2 + lsel)*16);
            uint32_t ah[4][4], bh[4][4];
#pragma unroll
            for (int i = 0; i < 4; ++i) {
                uint32_t ro = (uint32_t)((wm + i*16 + lrow)*ROWB) + chOff;
                ldsm4(ah[i], sb + SB_A + ro);
            }
#pragma unroll
            for (int j16 = 0; j16 < 4; ++j16) {
                uint32_t ro = (uint32_t)((wn + j16*16 + lrow)*ROWB) + chOff;
                ldsm4(bh[j16], sb + SB_B + ro);
            }
#pragma unroll
            for (int i = 0; i < 4; ++i)
#pragma unroll
                for (int j = 0; j < 8; ++j) {
                    int j16 = j >> 1, hf = j & 1;
                    hmma(acc[i][j], ah[i], bh[j16][hf], bh[j16][2 + hf]);
                }
        }
        __syncthreads();
    }

    int qrow = lane >> 2;
    int qcol = (lane & 3) * 2;
#pragma unroll
    for (int i = 0; i < 4; ++i) {
        int r0 = bm + wm + i*16 + qrow;
#pragma unroll
        for (int j = 0; j < 8; ++j) {
            int cc = bn + wn + j*8 + qcol;
            *(__half2*)&U[(size_t)r0*Nld + cc] =
                __floats2half2_rn(acc[i][j][0], acc[i][j][1]);
            *(__half2*)&U[(size_t)(r0 + 8)*Nld + cc] =
                __floats2half2_rn(acc[i][j][2], acc[i][j][3]);
        }
    }
}

// ============================ layer-0 GEMM (im2col folded into loads) ============================
// U0[l*512+n][j] = sum_k sum_c X[(l+k)*512+n][c] * Wt0[j][k*64+c]
// CTA 256x128 (rows = fixed l, n0 + 0..255), 8 chunks (k=0..7), K'=64 per chunk.
#define R0B    144
#define A0_MATB (256*R0B)              // 36864
#define B0_MATB (128*R0B)              // 18432
#define STAGE0B (A0_MATB + B0_MATB)    // 55296
#define NST0   3
#define GEMM0_DSMEM (NST0*STAGE0B)     // 165888

__device__ __forceinline__ void load_stage0(uint32_t sb, int kblk,
    const __half* __restrict__ X, const __half* __restrict__ Bw,
    int arow0, int bn, int tid) {
    // A: 256 rows x 8 x 16B = 2048 cp16 -> 8/thread ; arow0 = (l+k)*512 + n0
#pragma unroll
    for (int i = tid; i < 2048; i += 256) {
        int row = i >> 3, ch = i & 7;
        uint32_t so = (uint32_t)(row*R0B + ch*16);
        cp16(sb + so, X + (size_t)(arow0 + row)*C_ + ch*8);
    }
    // B: 128 rows x 8 x 16B = 1024 cp16 -> 4/thread
#pragma unroll
    for (int i = tid; i < 1024; i += 256) {
        int row = i >> 3, ch = i & 7;
        uint32_t so = (uint32_t)(A0_MATB + row*R0B + ch*16);
        cp16(sb + so, Bw + (size_t)(bn + row)*512 + kblk*64 + ch*8);
    }
}

__global__ __launch_bounds__(256) void kgemm0(
    const __half* __restrict__ X, const __half* __restrict__ Bw,
    __half* __restrict__ U) {
    extern __shared__ char dsm[];
    uint32_t dyn = smem_u32(dsm);
    int tid  = threadIdx.x;
    int wid  = tid >> 5, lane = tid & 31;
    int bm   = blockIdx.y * 256, bn = blockIdx.x * 128;
    int l    = bm >> 9;                // constant per CTA
    int n0   = bm & 511;               // 0 or 256
    int wm   = (wid >> 1) * 64;
    int wn   = (wid & 1)  * 64;

    int g = lane >> 3;
    int lrow = (g & 1) * 8 + (lane & 7);
    int lsel = g >> 1;

    float acc[4][8][4];
#pragma unroll
    for (int i = 0; i < 4; ++i)
#pragma unroll
        for (int j = 0; j < 8; ++j)
#pragma unroll
            for (int q = 0; q < 4; ++q) acc[i][j][q] = 0.f;

#pragma unroll
    for (int s = 0; s < NST0 - 1; ++s) {
        load_stage0(dyn + s*STAGE0B, s, X, Bw, (l + s)*N_ + n0, bn, tid);
        CP_COMMIT();
    }

    for (int c = 0; c < 8; ++c) {
        asm volatile("cp.async.wait_group %0;" :: "n"(NST0 - 2) : "memory");
        __syncthreads();
        int nx = c + NST0 - 1;
        if (nx < 8)
            load_stage0(dyn + (nx % NST0)*STAGE0B, nx, X, Bw, (l + nx)*N_ + n0, bn, tid);
        CP_COMMIT();

        uint32_t sb = dyn + (c % NST0)*STAGE0B;
#pragma unroll
        for (int kk = 0; kk < 4; ++kk) {       // K'=64 -> 4 k16 steps
            uint32_t chOff = (uint32_t)((kk*2 + lsel)*16);
            uint32_t ah[4][4], bh[4][4];
#pragma unroll
            for (int i = 0; i < 4; ++i) {
                uint32_t ro = (uint32_t)((wm + i*16 + lrow)*R0B) + chOff;
                ldsm4(ah[i], sb + ro);
            }
#pragma unroll
            for (int j16 = 0; j16 < 4; ++j16) {
                uint32_t ro = (uint32_t)(A0_MATB + (wn + j16*16 + lrow)*R0B) + chOff;
                ldsm4(bh[j16], sb + ro);
            }
#pragma unroll
            for (int i = 0; i < 4; ++i)
#pragma unroll
                for (int j = 0; j < 8; ++j) {
                    int j16 = j >> 1, hf = j & 1;
                    hmma(acc[i][j], ah[i], bh[j16][hf], bh[j16][2 + hf]);
                }
        }
        __syncthreads();
    }

    int qrow = lane >> 2;
    int qcol = (lane & 3) * 2;
#pragma unroll
    for (int i = 0; i < 4; ++i) {
        int r0 = bm + wm + i*16 + qrow;
#pragma unroll
        for (int j = 0; j < 8; ++j) {
            int cc = bn + wn + j*8 + qcol;
            *(__half2*)&U[(size_t)r0*1024 + cc] =
                __floats2half2_rn(acc[i][j][0], acc[i][j][1]);
            *(__half2*)&U[(size_t)(r0 + 8)*1024 + cc] =
                __floats2half2_rn(acc[i][j][2], acc[i][j][3]);
        }
    }
}

// ============================ SRU scan (fp16 U -> fp16 h) ============================
__global__ void kscan(const __half* __restrict__ U, __half* __restrict__ hout,
                      const float* __restrict__ bfp, const float* __restrict__ brp) {
    int n   = blockIdx.x;
    int dir = blockIdx.y;
    int h   = threadIdx.x;
    int base = dir * (4*H_) + h;
    float bfv = bfp[dir*H_ + h];
    float brv = brp[dir*H_ + h];
    int l    = dir ? (L_ - 1) : 0;
    int step = dir ? -1 : 1;
    float c = 0.f;

    size_t ro = ((size_t)(l * N_ + n)) * (8*H_) + base;
    float z  = __half2float(U[ro]);
    float fv = __half2float(U[ro + H_]);
    float rv = __half2float(U[ro + 2*H_]);
    float hp = __half2float(U[ro + 3*H_]);

    for (int it = 0; it < L_; ++it) {
        int lcur = l;
        int lnext = l + step;
        float zn = 0.f, fn = 0.f, rn = 0.f, hpn = 0.f;
        if (it + 1 < L_) {
            size_t ro2 = ((size_t)(lnext * N_ + n)) * (8*H_) + base;
            zn  = __half2float(U[ro2]);
            fn  = __half2float(U[ro2 + H_]);
            rn  = __half2float(U[ro2 + 2*H_]);
            hpn = __half2float(U[ro2 + 3*H_]);
        }
        float ff = 1.f / (1.f + __expf(-(fv + bfv)));
        float rr = 1.f / (1.f + __expf(-(rv + brv)));
        c = ff * c + (1.f - ff) * z;
        float o = rr * c + (1.f - rr) * hp;
        hout[((size_t)(lcur * N_ + n)) * (2*H_) + dir*H_ + h] = __float2half_rn(o);
        z = zn; fv = fn; rv = rn; hp = hpn;
        l = lnext;
    }
}

// ============================ conv-transpose gather + residual ============================
#define TFO 16
__global__ void kfinal(const __half* __restrict__ Y, const float* __restrict__ convb,
                       float* __restrict__ out) {
    __shared__ float sh[23 * 513];
    int n   = blockIdx.x;
    int fob = blockIdx.y * TFO;
    int tid = threadIdx.x;
    for (int i = tid; i < 23 * 512; i += 256) {
        int r = i >> 9, col = i & 511;
        int l = fob - 7 + r;
        float v = 0.f;
        if (l >= 0 && l < L_) v = __half2float(Y[((size_t)(l * N_ + n)) * 512 + col]);
        sh[r * 513 + col] = v;
    }
    __syncthreads();
    int fo_local = tid & 15;
    int cg = tid >> 4;
    int fo = fob + fo_local;
    int b = n >> 7, t = n & 127;
#pragma unroll
    for (int cc = 0; cc < 4; ++cc) {
        int c = cg * 4 + cc;
        float acc = convb[c];
#pragma unroll
        for (int k = 0; k < 8; ++k)
            acc += sh[(fo_local + 7 - k) * 513 + c * 8 + k];
        int oi = ((b*C_ + c)*T_ + t)*Fd_ + fo;
        out[oi] = acc + g_xn[oi];
    }
}

// ============================ launch ============================
extern "C" void kernel_launch(void* const* d_in, const int* in_sizes, int n_in,
                              void* d_out, int out_size) {
    const float* x     = (const float*)d_in[0];
    const float* gamma = (const float*)d_in[1];
    const float* beta  = (const float*)d_in[2];
    const float* W[4]  = {(const float*)d_in[3],  (const float*)d_in[6],
                          (const float*)d_in[9],  (const float*)d_in[12]};
    const float* bf[4] = {(const float*)d_in[4],  (const float*)d_in[7],
                          (const float*)d_in[10], (const float*)d_in[13]};
    const float* br[4] = {(const float*)d_in[5],  (const float*)d_in[8],
                          (const float*)d_in[11], (const float*)d_in[14]};
    const float* convW = (const float*)d_in[15];   // (2H, C, K) == (256, 512) row-major
    const float* convb = (const float*)d_in[16];
    float* out = (float*)d_out;

    void *pU, *pX, *ph, *pwh;
    cudaGetSymbolAddress(&pU,  g_U);
    cudaGetSymbolAddress(&pX,  g_X);
    cudaGetSymbolAddress(&ph,  g_h);
    cudaGetSymbolAddress(&pwh, g_Wh);
    __half* Wh = (__half*)pwh;
    const int woff[5] = {WOFF0, WOFF1, WOFF2, WOFF3, WOFFC};

    cudaFuncSetAttribute(kgemm,  cudaFuncAttributeMaxDynamicSharedMemorySize, GEMM_DSMEM);
    cudaFuncSetAttribute(kgemm0, cudaFuncAttributeMaxDynamicSharedMemorySize, GEMM0_DSMEM);

    knorm<<<(B_*T_*Fd_ + 255)/256, 256>>>(x, gamma, beta);

    // weights: W0 via permuted transpose; W1-3 + convW via standard transpose
    ktrans0<<<dim3(1024/32, 512/32), dim3(32,8)>>>(W[0], Wh + woff[0]);
    for (int i = 1; i < 4; ++i)
        ktrans<<<dim3(1024/32, 256/32), dim3(32,8)>>>(W[i], Wh + woff[i], 256, 1024);
    ktrans<<<dim3(512/32, 256/32), dim3(32,8)>>>(convW, Wh + woff[4], 256, 512);

    // layer 0: im2col-folded GEMM over X
    kgemm0<<<dim3(1024/128, M_/256), 256, GEMM0_DSMEM>>>(
        (const __half*)pX, Wh + woff[0], (__half*)pU);
    kscan<<<dim3(N_, 2), 128>>>((const __half*)pU, (__half*)ph, bf[0], br[0]);

    for (int i = 1; i < 4; ++i) {
        kgemm<<<dim3(1024/128, M_/256), 256, GEMM_DSMEM>>>(
            (const __half*)ph, Wh + woff[i], (__half*)pU, 256, 1024);
        kscan<<<dim3(N_, 2), 128>>>((const __half*)pU, (__half*)ph, bf[i], br[i]);
    }

    // conv-transpose as GEMM: Y (M x 512) = h (M x 256) @ convW^T-layout (512 x 256)
    kgemm<<<dim3(512/128, M_/256), 256, GEMM_DSMEM>>>(
        (const __half*)ph, Wh + woff[4], (__half*)pU, 256, 512);
    kfinal<<<dim3(N_, Fd_/TFO), 256>>>((const __half*)pU, convb, out);
}

// round 15
// speedup vs baseline: 4.2537x; 1.0896x over previous
#include <cuda_runtime.h>
#include <cuda_fp16.h>
#include <math.h>
#include <stdint.h>

#define B_  4
#define C_  64
#define T_  128
#define Fd_ 128
#define H_  128
#define K_  8
#define L_  121              // F - K + 1
#define N_  (B_*T_)          // 512
#define M_  (L_*N_)          // 61952
#define CK_ (C_*K_)          // 512

// weight scratch offsets (elements) for transposed fp16 weights
#define WOFF0 0
#define WOFF1 (1024*512)
#define WOFF2 (WOFF1 + 1024*256)
#define WOFF3 (WOFF2 + 1024*256)
#define WOFFC (WOFF3 + 1024*256)
#define WTOT  (WOFFC + 512*256)

// ---- scratch (device globals; no allocation allowed) ----
__device__ __half g_X  [Fd_*N_*C_];      //  8.4 MB  normed input fp16, layout [(f*512+n)*64+c]
__device__ __half g_h  [M_*2*H_];        // 31.7 MB  layer output fp16
__device__ __half g_U  [M_*8*H_];        // 126.9 MB GEMM output (fp16)
__device__ __half g_Wh [WTOT];           // transposed weights fp16

// ============================ helpers ============================
__device__ __forceinline__ uint32_t smem_u32(const void* p) {
    uint32_t a;
    asm("{ .reg .u64 t; cvta.to.shared.u64 t, %1; cvt.u32.u64 %0, t; }" : "=r"(a) : "l"(p));
    return a;
}
__device__ __forceinline__ void cp16(uint32_t s, const void* g) {
    asm volatile("cp.async.cg.shared.global [%0], [%1], 16;" :: "r"(s), "l"(g) : "memory");
}
#define CP_COMMIT() asm volatile("cp.async.commit_group;" ::: "memory")

__device__ __forceinline__ void ldsm4(uint32_t* r, uint32_t addr) {
    asm volatile("ldmatrix.sync.aligned.m8n8.x4.shared.b16 {%0,%1,%2,%3}, [%4];"
        : "=r"(r[0]), "=r"(r[1]), "=r"(r[2]), "=r"(r[3]) : "r"(addr));
}
__device__ __forceinline__ void hmma(float* c, const uint32_t* a, uint32_t b0, uint32_t b1) {
    asm volatile("mma.sync.aligned.m16n8k16.row.col.f32.f16.f16.f32 "
        "{%0,%1,%2,%3}, {%4,%5,%6,%7}, {%8,%9}, {%0,%1,%2,%3};"
        : "+f"(c[0]), "+f"(c[1]), "+f"(c[2]), "+f"(c[3])
        : "r"(a[0]), "r"(a[1]), "r"(a[2]), "r"(a[3]), "r"(b0), "r"(b1));
}

// ============================ channel norm (-> fp16 X) ============================
__global__ void knorm(const float* __restrict__ x, const float* __restrict__ gamma,
                      const float* __restrict__ beta) {
    int idx = blockIdx.x * blockDim.x + threadIdx.x;   // over B*T*F
    if (idx >= B_*T_*Fd_) return;
    int f = idx % Fd_;
    int t = (idx / Fd_) % T_;
    int b = idx / (T_*Fd_);
    int n = b*T_ + t;
    float v[C_];
    float s = 0.f;
#pragma unroll
    for (int c = 0; c < C_; ++c) {
        v[c] = x[((b*C_ + c)*T_ + t)*Fd_ + f];
        s += v[c];
    }
    float mu = s * (1.0f/C_);
    float vs = 0.f;
#pragma unroll
    for (int c = 0; c < C_; ++c) { float d = v[c]-mu; vs += d*d; }
    float inv = rsqrtf(vs*(1.0f/C_) + 1e-8f);
    __half hx[C_];
#pragma unroll
    for (int c = 0; c < C_; ++c)
        hx[c] = __float2half_rn(gamma[c]*(v[c]-mu)*inv + beta[c]);
    uint4* dst = (uint4*)&g_X[((size_t)f*N_ + n)*C_];
    const uint4* src = (const uint4*)hx;
#pragma unroll
    for (int q = 0; q < 8; ++q) dst[q] = src[q];
}

// ============ weight transpose to fp16: W (R x Cc) -> Wh[n][k] ============
__global__ void ktrans(const float* __restrict__ W, __half* __restrict__ wh,
                       int R, int Cc) {
    __shared__ float t[32][33];
    int c0 = blockIdx.x*32;
    int r0 = blockIdx.y*32;
    int tx = threadIdx.x, ty = threadIdx.y;
#pragma unroll
    for (int i = 0; i < 4; ++i)
        t[ty + i*8][tx] = W[(size_t)(r0 + ty + i*8)*Cc + c0 + tx];
    __syncthreads();
#pragma unroll
    for (int i = 0; i < 4; ++i) {
        int n = c0 + ty + i*8;
        int k = r0 + tx;
        wh[(size_t)n*R + k] = __float2half_rn(t[tx][ty + i*8]);
    }
}

// ============ layer-0 weight transpose with k-major permute ============
// Wt0[j][k*64 + c] = W0[c*8 + k][j]
__global__ void ktrans0(const float* __restrict__ W, __half* __restrict__ wt) {
    __shared__ float t[32][33];
    int c0 = blockIdx.x*32;            // over j (1024)
    int r0 = blockIdx.y*32;            // over ck (512)
    int tx = threadIdx.x, ty = threadIdx.y;
#pragma unroll
    for (int i = 0; i < 4; ++i)
        t[ty + i*8][tx] = W[(size_t)(r0 + ty + i*8)*1024 + c0 + tx];
    __syncthreads();
#pragma unroll
    for (int i = 0; i < 4; ++i) {
        int j  = c0 + ty + i*8;
        int ck = r0 + tx;
        int c = ck >> 3, k = ck & 7;
        wt[(size_t)j*512 + k*64 + c] = __float2half_rn(t[tx][ty + i*8]);
    }
}

// ============================ generic fp16 GEMM (layers 1-3, conv) ============================
// C(M x N) = A(M x K)*B(K x N); A fp16 [M][K], B fp16 transposed [N][K].
// CTA 128x128, 128 threads (4 warps, warp 64x64), BK=32, 4-stage, occupancy 2.
#define ROWB   80
#define A_MATB (128*ROWB)
#define B_MATB (128*ROWB)
#define SB_A   0
#define SB_B   A_MATB
#define STAGEB (A_MATB + B_MATB)       // 20480
#define NSTAGE 4
#define GEMM_DSMEM (NSTAGE*STAGEB)     // 81920

__device__ __forceinline__ void load_stage(uint32_t sb, int k0,
    const __half* __restrict__ A, const __half* __restrict__ Bh,
    int K, int bm, int bn, int tid) {
#pragma unroll
    for (int i = tid; i < 512; i += 128) {
        int row = i >> 2, ch = i & 3;
        uint32_t so = (uint32_t)(row*ROWB + ch*16);
        cp16(sb + SB_A + so, A + (size_t)(bm + row)*K + k0 + ch*8);
        cp16(sb + SB_B + so, Bh + (size_t)(bn + row)*K + k0 + ch*8);
    }
}

__global__ __launch_bounds__(128) void kgemm(
    const __half* __restrict__ A, const __half* __restrict__ Bh,
    __half* __restrict__ U, int K, int Nld) {
    extern __shared__ char dsm[];
    uint32_t dyn = smem_u32(dsm);
    int tid  = threadIdx.x;
    int wid  = tid >> 5, lane = tid & 31;
    int bm   = blockIdx.y * 128, bn = blockIdx.x * 128;
    int wm   = (wid >> 1) * 64;        // warp m offset (0,64)
    int wn   = (wid & 1)  * 64;        // warp n offset (0,64)

    int g = lane >> 3;
    int lrow = (g & 1) * 8 + (lane & 7);
    int lsel = g >> 1;

    float acc[4][8][4];
#pragma unroll
    for (int i = 0; i < 4; ++i)
#pragma unroll
        for (int j = 0; j < 8; ++j)
#pragma unroll
            for (int q = 0; q < 4; ++q) acc[i][j][q] = 0.f;

    int nc = K >> 5;
#pragma unroll
    for (int s = 0; s < NSTAGE - 1; ++s) {
        if (s < nc) load_stage(dyn + s*STAGEB, s*32, A, Bh, K, bm, bn, tid);
        CP_COMMIT();
    }

    for (int c = 0; c < nc; ++c) {
        asm volatile("cp.async.wait_group %0;" :: "n"(NSTAGE - 2) : "memory");
        __syncthreads();
        int nx = c + NSTAGE - 1;
        if (nx < nc)
            load_stage(dyn + (nx % NSTAGE)*STAGEB, nx*32, A, Bh, K, bm, bn, tid);
        CP_COMMIT();

        uint32_t sb = dyn + (c % NSTAGE)*STAGEB;
#pragma unroll
        for (int kk = 0; kk < 2; ++kk) {
            uint32_t chOff = (uint32_t)((kk*2 + lsel)*16);
            uint32_t ah[4][4], bh[4][4];
#pragma unroll
            for (int i = 0; i < 4; ++i) {
                uint32_t ro = (uint32_t)((wm + i*16 + lrow)*ROWB) + chOff;
                ldsm4(ah[i], sb + SB_A + ro);
            }
#pragma unroll
            for (int j16 = 0; j16 < 4; ++j16) {
                uint32_t ro = (uint32_t)((wn + j16*16 + lrow)*ROWB) + chOff;
                ldsm4(bh[j16], sb + SB_B + ro);
            }
#pragma unroll
            for (int i = 0; i < 4; ++i)
#pragma unroll
                for (int j = 0; j < 8; ++j) {
                    int j16 = j >> 1, hf = j & 1;
                    hmma(acc[i][j], ah[i], bh[j16][hf], bh[j16][2 + hf]);
                }
        }
    }

    int qrow = lane >> 2;
    int qcol = (lane & 3) * 2;
#pragma unroll
    for (int i = 0; i < 4; ++i) {
        int r0 = bm + wm + i*16 + qrow;
#pragma unroll
        for (int j = 0; j < 8; ++j) {
            int cc = bn + wn + j*8 + qcol;
            *(__half2*)&U[(size_t)r0*Nld + cc] =
                __floats2half2_rn(acc[i][j][0], acc[i][j][1]);
            *(__half2*)&U[(size_t)(r0 + 8)*Nld + cc] =
                __floats2half2_rn(acc[i][j][2], acc[i][j][3]);
        }
    }
}

// ============================ layer-0 GEMM (im2col folded into loads) ============================
// U0[l*512+n][j] = sum_k sum_c X[(l+k)*512+n][c] * Wt0[j][k*64+c]
// CTA 128x128 (rows: fixed l, 128 n's), 8 chunks (k), K'=64 per chunk, occupancy 2.
#define R0B    144
#define A0_MATB (128*R0B)              // 18432
#define B0_MATB (128*R0B)              // 18432
#define STAGE0B (A0_MATB + B0_MATB)    // 36864
#define NST0   3
#define GEMM0_DSMEM (NST0*STAGE0B)     // 110592

__device__ __forceinline__ void load_stage0(uint32_t sb, int kblk,
    const __half* __restrict__ X, const __half* __restrict__ Bw,
    int arow0, int bn, int tid) {
#pragma unroll
    for (int i = tid; i < 1024; i += 128) {
        int row = i >> 3, ch = i & 7;
        uint32_t so = (uint32_t)(row*R0B + ch*16);
        cp16(sb + so, X + (size_t)(arow0 + row)*C_ + ch*8);
        cp16(sb + A0_MATB + so, Bw + (size_t)(bn + row)*512 + kblk*64 + ch*8);
    }
}

__global__ __launch_bounds__(128) void kgemm0(
    const __half* __restrict__ X, const __half* __restrict__ Bw,
    __half* __restrict__ U) {
    extern __shared__ char dsm[];
    uint32_t dyn = smem_u32(dsm);
    int tid  = threadIdx.x;
    int wid  = tid >> 5, lane = tid & 31;
    int bm   = blockIdx.y * 128, bn = blockIdx.x * 128;
    int l    = bm >> 9;
    int n0   = bm & 511;
    int wm   = (wid >> 1) * 64;
    int wn   = (wid & 1)  * 64;

    int g = lane >> 3;
    int lrow = (g & 1) * 8 + (lane & 7);
    int lsel = g >> 1;

    float acc[4][8][4];
#pragma unroll
    for (int i = 0; i < 4; ++i)
#pragma unroll
        for (int j = 0; j < 8; ++j)
#pragma unroll
            for (int q = 0; q < 4; ++q) acc[i][j][q] = 0.f;

#pragma unroll
    for (int s = 0; s < NST0 - 1; ++s) {
        load_stage0(dyn + s*STAGE0B, s, X, Bw, (l + s)*N_ + n0, bn, tid);
        CP_COMMIT();
    }

    for (int c = 0; c < 8; ++c) {
        asm volatile("cp.async.wait_group %0;" :: "n"(NST0 - 2) : "memory");
        __syncthreads();
        int nx = c + NST0 - 1;
        if (nx < 8)
            load_stage0(dyn + (nx % NST0)*STAGE0B, nx, X, Bw, (l + nx)*N_ + n0, bn, tid);
        CP_COMMIT();

        uint32_t sb = dyn + (c % NST0)*STAGE0B;
#pragma unroll
        for (int kk = 0; kk < 4; ++kk) {
            uint32_t chOff = (uint32_t)((kk*2 + lsel)*16);
            uint32_t ah[4][4], bh[4][4];
#pragma unroll
            for (int i = 0; i < 4; ++i) {
                uint32_t ro = (uint32_t)((wm + i*16 + lrow)*R0B) + chOff;
                ldsm4(ah[i], sb + ro);
            }
#pragma unroll
            for (int j16 = 0; j16 < 4; ++j16) {
                uint32_t ro = (uint32_t)(A0_MATB + (wn + j16*16 + lrow)*R0B) + chOff;
                ldsm4(bh[j16], sb + ro);
            }
#pragma unroll
            for (int i = 0; i < 4; ++i)
#pragma unroll
                for (int j = 0; j < 8; ++j) {
                    int j16 = j >> 1, hf = j & 1;
                    hmma(acc[i][j], ah[i], bh[j16][hf], bh[j16][2 + hf]);
                }
        }
    }

    int qrow = lane >> 2;
    int qcol = (lane & 3) * 2;
#pragma unroll
    for (int i = 0; i < 4; ++i) {
        int r0 = bm + wm + i*16 + qrow;
#pragma unroll
        for (int j = 0; j < 8; ++j) {
            int cc = bn + wn + j*8 + qcol;
            *(__half2*)&U[(size_t)r0*1024 + cc] =
                __floats2half2_rn(acc[i][j][0], acc[i][j][1]);
            *(__half2*)&U[(size_t)(r0 + 8)*1024 + cc] =
                __floats2half2_rn(acc[i][j][2], acc[i][j][3]);
        }
    }
}

// ============================ SRU scan (half2-vectorized) ============================
// block: 128 threads = 2 dirs x 64 half2-lanes; grid: N_ blocks.
__global__ void kscan(const __half* __restrict__ U, __half* __restrict__ hout,
                      const float* __restrict__ bfp, const float* __restrict__ brp) {
    int n   = blockIdx.x;
    int tid = threadIdx.x;
    int dir = tid >> 6;
    int j   = tid & 63;                // half2 lane: h = 2j, 2j+1
    float bf0 = bfp[dir*H_ + 2*j],  bf1 = bfp[dir*H_ + 2*j + 1];
    float br0 = brp[dir*H_ + 2*j],  br1 = brp[dir*H_ + 2*j + 1];
    int l    = dir ? (L_ - 1) : 0;
    int step = dir ? -1 : 1;
    float c0 = 0.f, c1 = 0.f;

    const __half2* U2 = (const __half2*)U;     // row = 512 half2
    __half2* h2out    = (__half2*)hout;        // row = 128 half2
    int base = dir*256 + j;

    size_t ro = ((size_t)(l * N_ + n)) * 512 + base;
    __half2 z2  = U2[ro];
    __half2 f2  = U2[ro + 64];
    __half2 r2  = U2[ro + 128];
    __half2 hp2 = U2[ro + 192];

    for (int it = 0; it < L_; ++it) {
        int lcur = l;
        int lnext = l + step;
        __half2 zn, fn, rn, hpn;
        if (it + 1 < L_) {
            size_t ro2 = ((size_t)(lnext * N_ + n)) * 512 + base;
            zn  = U2[ro2];
            fn  = U2[ro2 + 64];
            rn  = U2[ro2 + 128];
            hpn = U2[ro2 + 192];
        } else {
            zn = fn = rn = hpn = __float2half2_rn(0.f);
        }
        float2 zf = __half22float2(z2),  ff2 = __half22float2(f2);
        float2 rf = __half22float2(r2),  hf2 = __half22float2(hp2);
        float fg0 = 1.f / (1.f + __expf(-(ff2.x + bf0)));
        float fg1 = 1.f / (1.f + __expf(-(ff2.y + bf1)));
        float rg0 = 1.f / (1.f + __expf(-(rf.x + br0)));
        float rg1 = 1.f / (1.f + __expf(-(rf.y + br1)));
        c0 = fg0 * c0 + (1.f - fg0) * zf.x;
        c1 = fg1 * c1 + (1.f - fg1) * zf.y;
        float o0 = rg0 * c0 + (1.f - rg0) * hf2.x;
        float o1 = rg1 * c1 + (1.f - rg1) * hf2.y;
        h2out[((size_t)(lcur * N_ + n)) * 128 + dir*64 + j] = __floats2half2_rn(o0, o1);
        z2 = zn; f2 = fn; r2 = rn; hp2 = hpn;
        l = lnext;
    }
}

// ============================ conv-transpose gather + residual ============================
#define TFO 16
__global__ void kfinal(const __half* __restrict__ Y, const float* __restrict__ convb,
                       float* __restrict__ out) {
    __shared__ float sh[23 * 513];
    int n   = blockIdx.x;
    int fob = blockIdx.y * TFO;
    int tid = threadIdx.x;
    const __half2* Y2 = (const __half2*)Y;     // row = 256 half2
    for (int i = tid; i < 23 * 256; i += 256) {
        int r = i >> 8, c2 = i & 255;
        int l = fob - 7 + r;
        float2 v = make_float2(0.f, 0.f);
        if (l >= 0 && l < L_) v = __half22float2(Y2[((size_t)(l * N_ + n)) * 256 + c2]);
        sh[r * 513 + 2*c2]     = v.x;
        sh[r * 513 + 2*c2 + 1] = v.y;
    }
    __syncthreads();
    int fo_local = tid & 15;
    int cg = tid >> 4;
    int fo = fob + fo_local;
    int b = n >> 7, t = n & 127;
#pragma unroll
    for (int cc = 0; cc < 4; ++cc) {
        int c = cg * 4 + cc;
        float acc = convb[c];
#pragma unroll
        for (int k = 0; k < 8; ++k)
            acc += sh[(fo_local + 7 - k) * 513 + c * 8 + k];
        float xr = __half2float(g_X[((size_t)fo*N_ + n)*C_ + c]);
        out[((b*C_ + c)*T_ + t)*Fd_ + fo] = acc + xr;
    }
}

// ============================ launch ============================
extern "C" void kernel_launch(void* const* d_in, const int* in_sizes, int n_in,
                              void* d_out, int out_size) {
    const float* x     = (const float*)d_in[0];
    const float* gamma = (const float*)d_in[1];
    const float* beta  = (const float*)d_in[2];
    const float* W[4]  = {(const float*)d_in[3],  (const float*)d_in[6],
                          (const float*)d_in[9],  (const float*)d_in[12]};
    const float* bf[4] = {(const float*)d_in[4],  (const float*)d_in[7],
                          (const float*)d_in[10], (const float*)d_in[13]};
    const float* br[4] = {(const float*)d_in[5],  (const float*)d_in[8],
                          (const float*)d_in[11], (const float*)d_in[14]};
    const float* convW = (const float*)d_in[15];   // (2H, C, K) == (256, 512) row-major
    const float* convb = (const float*)d_in[16];
    float* out = (float*)d_out;

    void *pU, *pX, *ph, *pwh;
    cudaGetSymbolAddress(&pU,  g_U);
    cudaGetSymbolAddress(&pX,  g_X);
    cudaGetSymbolAddress(&ph,  g_h);
    cudaGetSymbolAddress(&pwh, g_Wh);
    __half* Wh = (__half*)pwh;
    const int woff[5] = {WOFF0, WOFF1, WOFF2, WOFF3, WOFFC};

    cudaFuncSetAttribute(kgemm,  cudaFuncAttributeMaxDynamicSharedMemorySize, GEMM_DSMEM);
    cudaFuncSetAttribute(kgemm0, cudaFuncAttributeMaxDynamicSharedMemorySize, GEMM0_DSMEM);

    knorm<<<(B_*T_*Fd_ + 255)/256, 256>>>(x, gamma, beta);

    // weights: W0 via permuted transpose; W1-3 + convW via standard transpose
    ktrans0<<<dim3(1024/32, 512/32), dim3(32,8)>>>(W[0], Wh + woff[0]);
    for (int i = 1; i < 4; ++i)
        ktrans<<<dim3(1024/32, 256/32), dim3(32,8)>>>(W[i], Wh + woff[i], 256, 1024);
    ktrans<<<dim3(512/32, 256/32), dim3(32,8)>>>(convW, Wh + woff[4], 256, 512);

    // layer 0: im2col-folded GEMM over X
    kgemm0<<<dim3(1024/128, M_/128), 128, GEMM0_DSMEM>>>(
        (const __half*)pX, Wh + woff[0], (__half*)pU);
    kscan<<<N_, 128>>>((const __half*)pU, (__half*)ph, bf[0], br[0]);

    for (int i = 1; i < 4; ++i) {
        kgemm<<<dim3(1024/128, M_/128), 128, GEMM_DSMEM>>>(
            (const __half*)ph, Wh + woff[i], (__half*)pU, 256, 1024);
        kscan<<<N_, 128>>>((const __half*)pU, (__half*)ph, bf[i], br[i]);
    }

    // conv-transpose as GEMM: Y (M x 512) = h (M x 256) @ convW^T-layout (512 x 256)
    kgemm<<<dim3(512/128, M_/128), 128, GEMM_DSMEM>>>(
        (const __half*)ph, Wh + woff[4], (__half*)pU, 256, 512);
    kfinal<<<dim3(N_, Fd_/TFO), 256>>>((const __half*)pU, convb, out);
}